// round 1
// baseline (speedup 1.0000x reference)
#include <cuda_runtime.h>
#include <math.h>

// Problem constants
#define B_ 4
#define N_ 96
#define P_ 64
#define C_ 1024
#define H_ 16
#define HD_ 64
#define M_ROWS (B_*N_*P_)   // 24576

// Scratch (device globals: allocation-free contract)
__device__ float g_xbar[B_*N_*C_];        // 384 x 1024 pooled input
__device__ float g_qk[B_*N_*2*C_];        // 384 x 2048 (q | k)
__device__ float g_attn[B_*H_*N_*N_];     // 64 x 96 x 96
__device__ float g_v[M_ROWS*C_];          // 24576 x 1024  (x @ W_v)
__device__ float g_o[M_ROWS*C_];          // 24576 x 1024  (attn-applied)

// ---------------------------------------------------------------------------
// 1) Mean-pool x over patches: xbar[b,n,c] = mean_p x[b,n,p,c]
// ---------------------------------------------------------------------------
__global__ void pool_kernel(const float* __restrict__ x, float* __restrict__ xbar) {
    int bn = blockIdx.x;                       // 0..383
    const float* xp = x + (size_t)bn * P_ * C_;
    for (int c = threadIdx.x; c < C_; c += 256) {
        float s = 0.f;
        #pragma unroll 8
        for (int p = 0; p < P_; ++p) s += xp[(size_t)p * C_ + c];
        xbar[(size_t)bn * C_ + c] = s * (1.0f / 64.0f);
    }
}

// ---------------------------------------------------------------------------
// Generic fp32 GEMM: C = A[M,K] * B[K,N] (+bias). 128x128 tile, BK=8, 8x8/thread
// All dims here are multiples of the tile sizes -> no edge guards.
// ---------------------------------------------------------------------------
#define BM 128
#define BN 128
#define BK 8
__global__ void __launch_bounds__(256) sgemm_kernel(
    const float* __restrict__ A, const float* __restrict__ Bm,
    float* __restrict__ Cm, const float* __restrict__ bias,
    int M, int N, int K, int lda, int ldb, int ldc, int hasBias)
{
    __shared__ float As[BK][BM + 4];   // padded: conflict-free transposed stores
    __shared__ float Bs[BK][BN];

    int tid = threadIdx.x;
    const float* Ab = A + (size_t)blockIdx.y * BM * lda;
    const float* Bb = Bm + (size_t)blockIdx.x * BN;

    int arow = tid >> 1, acol = (tid & 1) * 4;     // A: 128 rows x 8 k (float4)
    int brow = tid >> 5, bcol = (tid & 31) * 4;    // B: 8 rows x 128 cols (float4)
    int ty = tid >> 4, tx = tid & 15;

    float acc[8][8];
    #pragma unroll
    for (int i = 0; i < 8; ++i)
        #pragma unroll
        for (int j = 0; j < 8; ++j) acc[i][j] = 0.f;

    for (int k0 = 0; k0 < K; k0 += BK) {
        float4 av = *(const float4*)(Ab + (size_t)arow * lda + k0 + acol);
        As[acol + 0][arow] = av.x;
        As[acol + 1][arow] = av.y;
        As[acol + 2][arow] = av.z;
        As[acol + 3][arow] = av.w;
        float4 bv = *(const float4*)(Bb + (size_t)(k0 + brow) * ldb + bcol);
        *(float4*)&Bs[brow][bcol] = bv;
        __syncthreads();

        #pragma unroll
        for (int k = 0; k < BK; ++k) {
            float4 a0 = *(const float4*)&As[k][ty * 8];
            float4 a1 = *(const float4*)&As[k][ty * 8 + 4];
            float4 b0 = *(const float4*)&Bs[k][tx * 8];
            float4 b1 = *(const float4*)&Bs[k][tx * 8 + 4];
            float a[8] = {a0.x,a0.y,a0.z,a0.w,a1.x,a1.y,a1.z,a1.w};
            float b[8] = {b0.x,b0.y,b0.z,b0.w,b1.x,b1.y,b1.z,b1.w};
            #pragma unroll
            for (int i = 0; i < 8; ++i)
                #pragma unroll
                for (int j = 0; j < 8; ++j) acc[i][j] += a[i] * b[j];
        }
        __syncthreads();
    }

    int row0 = blockIdx.y * BM + ty * 8;
    int col0 = blockIdx.x * BN + tx * 8;
    float bb[8];
    #pragma unroll
    for (int j = 0; j < 8; ++j) bb[j] = hasBias ? bias[col0 + j] : 0.f;
    #pragma unroll
    for (int i = 0; i < 8; ++i) {
        float* cp = Cm + (size_t)(row0 + i) * ldc + col0;
        float4 o0 = make_float4(acc[i][0]+bb[0], acc[i][1]+bb[1], acc[i][2]+bb[2], acc[i][3]+bb[3]);
        float4 o1 = make_float4(acc[i][4]+bb[4], acc[i][5]+bb[5], acc[i][6]+bb[6], acc[i][7]+bb[7]);
        *(float4*)cp       = o0;
        *(float4*)(cp + 4) = o1;
    }
}

// ---------------------------------------------------------------------------
// 3) Scores + softmax. One block per (b,h). qk: [384, 2048] = [q(1024) | k(1024)]
//    attn[b,h,n,m] = softmax_m( q(b,n,h,:) . k(b,m,h,:) / 8 )
// ---------------------------------------------------------------------------
__global__ void attn_kernel(const float* __restrict__ qk, float* __restrict__ attn) {
    __shared__ float qs[N_][HD_];
    __shared__ float ks[N_][HD_];
    int b = blockIdx.x >> 4, h = blockIdx.x & 15;

    for (int i = threadIdx.x; i < N_ * HD_; i += 128) {
        int n = i >> 6, d = i & 63;
        const float* base = qk + ((size_t)(b * N_ + n)) * (2 * C_) + h * HD_ + d;
        qs[n][d] = base[0];
        ks[n][d] = base[C_];
    }
    __syncthreads();

    int n = threadIdx.x;
    if (n < N_) {
        float* row = attn + ((size_t)blockIdx.x * N_ + n) * N_;
        float mx = -1e30f;
        for (int m = 0; m < N_; ++m) {
            float dot = 0.f;
            #pragma unroll
            for (int d = 0; d < HD_; ++d) dot += qs[n][d] * ks[m][d];
            dot *= 0.125f;   // 1/sqrt(64)
            row[m] = dot;
            mx = fmaxf(mx, dot);
        }
        float sum = 0.f;
        for (int m = 0; m < N_; ++m) { float e = __expf(row[m] - mx); row[m] = e; sum += e; }
        float inv = 1.f / sum;
        for (int m = 0; m < N_; ++m) row[m] *= inv;
    }
}

// ---------------------------------------------------------------------------
// 5) Attention apply: out[b,n,p,c] = sum_m attn[b,h(c),n,m] * v[b,m,p,c]
//    Block = (b,p,h, n-half). smem: v tile [96 m x 64 c], attn tile [48 n x 96 m]
// ---------------------------------------------------------------------------
__global__ void __launch_bounds__(256) apply_kernel(
    const float* __restrict__ v, const float* __restrict__ attn, float* __restrict__ out)
{
    __shared__ float vs[N_][HD_];       // 24 KB
    __shared__ float as[48][N_ + 1];    // padded (97) -> conflict-free attn reads

    int bph = blockIdx.x;
    int h = bph & 15;
    int p = (bph >> 4) & 63;
    int b = bph >> 10;
    int n0 = blockIdx.y * 48;

    const float* vbase = v + ((size_t)b * N_ * P_ + p) * C_ + h * HD_;
    for (int i = threadIdx.x; i < N_ * (HD_ / 4); i += 256) {
        int m = i >> 4, c4 = i & 15;
        *(float4*)&vs[m][c4 * 4] = *(const float4*)(vbase + (size_t)m * P_ * C_ + c4 * 4);
    }
    const float* abase = attn + ((size_t)(b * H_ + h) * N_ + n0) * N_;
    for (int i = threadIdx.x; i < 48 * N_; i += 256) {
        int n = i / N_, m = i - n * N_;
        as[n][m] = abase[(size_t)n * N_ + m];
    }
    __syncthreads();

    int tx = threadIdx.x & 15, ty = threadIdx.x >> 4;
    float acc[3][4] = {};
    for (int m = 0; m < N_; ++m) {
        float4 vv = *(const float4*)&vs[m][tx * 4];
        #pragma unroll
        for (int i = 0; i < 3; ++i) {
            float a = as[ty * 3 + i][m];
            acc[i][0] += a * vv.x; acc[i][1] += a * vv.y;
            acc[i][2] += a * vv.z; acc[i][3] += a * vv.w;
        }
    }
    float* obase = out + ((size_t)b * N_ * P_ + p) * C_ + h * HD_ + tx * 4;
    #pragma unroll
    for (int i = 0; i < 3; ++i) {
        int n = n0 + ty * 3 + i;
        *(float4*)(obase + (size_t)n * P_ * C_) =
            make_float4(acc[i][0], acc[i][1], acc[i][2], acc[i][3]);
    }
}

// ---------------------------------------------------------------------------
extern "C" void kernel_launch(void* const* d_in, const int* in_sizes, int n_in,
                              void* d_out, int out_size)
{
    const float* x     = (const float*)d_in[0];  // (4,96,64,1024)
    const float* Wqkv  = (const float*)d_in[1];  // (1024, 3072)
    const float* Wproj = (const float*)d_in[2];  // (1024, 1024)
    const float* bproj = (const float*)d_in[3];  // (1024,)
    float* out = (float*)d_out;

    float *xbar, *qkbuf, *attnbuf, *vbuf, *obuf;
    cudaGetSymbolAddress((void**)&xbar,    g_xbar);
    cudaGetSymbolAddress((void**)&qkbuf,   g_qk);
    cudaGetSymbolAddress((void**)&attnbuf, g_attn);
    cudaGetSymbolAddress((void**)&vbuf,    g_v);
    cudaGetSymbolAddress((void**)&obuf,    g_o);

    // 1) pool
    pool_kernel<<<B_ * N_, 256>>>(x, xbar);
    // 2) q,k = xbar @ W_qkv[:, 0:2048]   (M=384, N=2048, K=1024)
    sgemm_kernel<<<dim3(2048 / BN, 384 / BM), 256>>>(
        xbar, Wqkv, qkbuf, nullptr, 384, 2048, 1024, C_, 3 * C_, 2 * C_, 0);
    // 3) scores + softmax
    attn_kernel<<<B_ * H_, 128>>>(qkbuf, attnbuf);
    // 4) v = x @ W_qkv[:, 2048:3072]     (M=24576, N=1024, K=1024)
    sgemm_kernel<<<dim3(C_ / BN, M_ROWS / BM), 256>>>(
        x, Wqkv + 2 * C_, vbuf, nullptr, M_ROWS, C_, C_, C_, 3 * C_, C_, 0);
    // 5) attention apply
    apply_kernel<<<dim3(B_ * P_ * H_, 2), 256>>>(vbuf, attnbuf, obuf);
    // 6) y = o @ W_proj + b_proj          (M=24576, N=1024, K=1024)
    sgemm_kernel<<<dim3(C_ / BN, M_ROWS / BM), 256>>>(
        obuf, Wproj, out, bproj, M_ROWS, C_, C_, C_, C_, C_, 1);
}

// round 3
// speedup vs baseline: 1.5744x; 1.5744x over previous
#include <cuda_runtime.h>
#include <math.h>
#include <stdint.h>

// Problem constants
#define B_ 4
#define N_ 96
#define P_ 64
#define C_ 1024
#define H_ 16
#define HD_ 64
#define M_ROWS (B_*N_*P_)   // 24576

// Scratch (device globals: allocation-free contract)
__device__ float g_xbar[B_*N_*C_];        // 384 x 1024 pooled input
__device__ float g_qk[B_*N_*2*C_];        // 384 x 2048 (q | k)
__device__ float g_attn[B_*H_*N_*N_];     // 64 x 96 x 96
__device__ float g_v[M_ROWS*C_];          // 24576 x 1024  (x @ W_v)
__device__ float g_o[M_ROWS*C_];          // 24576 x 1024  (attn-applied)

// ---------------------------------------------------------------------------
// 1) Mean-pool x over patches
// ---------------------------------------------------------------------------
__global__ void pool_kernel(const float* __restrict__ x, float* __restrict__ xbar) {
    int bn = blockIdx.x;
    const float* xp = x + (size_t)bn * P_ * C_;
    for (int c = threadIdx.x; c < C_; c += 256) {
        float s = 0.f;
        #pragma unroll 8
        for (int p = 0; p < P_; ++p) s += xp[(size_t)p * C_ + c];
        xbar[(size_t)bn * C_ + c] = s * (1.0f / 64.0f);
    }
}

// ---------------------------------------------------------------------------
// fp32 SIMT GEMM (kept for the small, precision-sensitive q/k projection)
// ---------------------------------------------------------------------------
#define BM 128
#define BN 128
#define BK 8
__global__ void __launch_bounds__(256) sgemm_kernel(
    const float* __restrict__ A, const float* __restrict__ Bm,
    float* __restrict__ Cm, int M, int N, int K, int lda, int ldb, int ldc)
{
    __shared__ float As[BK][BM + 4];
    __shared__ float Bs[BK][BN];
    int tid = threadIdx.x;
    const float* Ab = A + (size_t)blockIdx.y * BM * lda;
    const float* Bb = Bm + (size_t)blockIdx.x * BN;
    int arow = tid >> 1, acol = (tid & 1) * 4;
    int brow = tid >> 5, bcol = (tid & 31) * 4;
    int ty = tid >> 4, tx = tid & 15;
    float acc[8][8];
    #pragma unroll
    for (int i = 0; i < 8; ++i)
        #pragma unroll
        for (int j = 0; j < 8; ++j) acc[i][j] = 0.f;
    for (int k0 = 0; k0 < K; k0 += BK) {
        float4 av = *(const float4*)(Ab + (size_t)arow * lda + k0 + acol);
        As[acol + 0][arow] = av.x; As[acol + 1][arow] = av.y;
        As[acol + 2][arow] = av.z; As[acol + 3][arow] = av.w;
        float4 bv = *(const float4*)(Bb + (size_t)(k0 + brow) * ldb + bcol);
        *(float4*)&Bs[brow][bcol] = bv;
        __syncthreads();
        #pragma unroll
        for (int k = 0; k < BK; ++k) {
            float4 a0 = *(const float4*)&As[k][ty * 8];
            float4 a1 = *(const float4*)&As[k][ty * 8 + 4];
            float4 b0 = *(const float4*)&Bs[k][tx * 8];
            float4 b1 = *(const float4*)&Bs[k][tx * 8 + 4];
            float a[8] = {a0.x,a0.y,a0.z,a0.w,a1.x,a1.y,a1.z,a1.w};
            float b[8] = {b0.x,b0.y,b0.z,b0.w,b1.x,b1.y,b1.z,b1.w};
            #pragma unroll
            for (int i = 0; i < 8; ++i)
                #pragma unroll
                for (int j = 0; j < 8; ++j) acc[i][j] += a[i] * b[j];
        }
        __syncthreads();
    }
    int row0 = blockIdx.y * BM + ty * 8;
    int col0 = blockIdx.x * BN + tx * 8;
    #pragma unroll
    for (int i = 0; i < 8; ++i) {
        float* cp = Cm + (size_t)(row0 + i) * ldc + col0;
        *(float4*)cp       = make_float4(acc[i][0], acc[i][1], acc[i][2], acc[i][3]);
        *(float4*)(cp + 4) = make_float4(acc[i][4], acc[i][5], acc[i][6], acc[i][7]);
    }
}

// ---------------------------------------------------------------------------
// TF32 tensor-core GEMM: C = A[M,K] @ B[K,N] (+bias), row-major, tiles 128x128x16
// 8 warps: 2 (M) x 4 (N); warp tile 64x32; mma.sync.m16n8k8.tf32
// ---------------------------------------------------------------------------
__device__ __forceinline__ uint32_t f2tf(float f) {
    uint32_t r; asm("cvt.rna.tf32.f32 %0, %1;" : "=r"(r) : "f"(f)); return r;
}
__device__ __forceinline__ float f2tff(float f) { return __uint_as_float(f2tf(f)); }

#define LDSM4(R0,R1,R2,R3,ADDR) \
    asm volatile("ldmatrix.sync.aligned.m8n8.x4.shared.b16 {%0,%1,%2,%3}, [%4];" \
        : "=r"(R0),"=r"(R1),"=r"(R2),"=r"(R3) : "r"(ADDR))

#define MMA_TF32(C0,C1,C2,C3,A0,A1,A2,A3,B0,B1) \
    asm volatile("mma.sync.aligned.m16n8k8.row.col.f32.tf32.tf32.f32 " \
        "{%0,%1,%2,%3}, {%4,%5,%6,%7}, {%8,%9}, {%0,%1,%2,%3};" \
        : "+f"(C0),"+f"(C1),"+f"(C2),"+f"(C3) \
        : "r"(A0),"r"(A1),"r"(A2),"r"(A3),"r"(B0),"r"(B1))

#define SA_STRIDE 20   // floats per row; 8 rows x stride-20 spans all 32 banks

__global__ void __launch_bounds__(256) tf32_gemm(
    const float* __restrict__ A, const float* __restrict__ Bm,
    float* __restrict__ Cm, const float* __restrict__ bias,
    int M, int N, int K, int lda, int ldb, int ldc)
{
    __shared__ __align__(16) float As[2][128 * SA_STRIDE];  // [m][k]
    __shared__ __align__(16) float Bs[2][128 * SA_STRIDE];  // [n][k] (transposed)

    int tid = threadIdx.x;
    int lane = tid & 31, warp = tid >> 5;
    int wm = warp & 1, wn = warp >> 1;

    const float* Ab = A + (size_t)blockIdx.y * 128 * lda;
    const float* Bb = Bm + (size_t)blockIdx.x * 128;

    float acc[4][4][4];
    #pragma unroll
    for (int i = 0; i < 4; ++i)
        #pragma unroll
        for (int j = 0; j < 4; ++j)
            #pragma unroll
            for (int r = 0; r < 4; ++r) acc[i][j][r] = 0.f;

    float4 pa[2], pb[2];
    auto loadT = [&](int kt) {
        #pragma unroll
        for (int it = 0; it < 2; ++it) {
            int idx = tid + it * 256;
            int arow = idx >> 2, ach = idx & 3;
            pa[it] = *(const float4*)(Ab + (size_t)arow * lda + kt * 16 + ach * 4);
            int krow = idx >> 5, nch = idx & 31;
            pb[it] = *(const float4*)(Bb + (size_t)(kt * 16 + krow) * ldb + nch * 4);
        }
    };
    auto storeT = [&](int buf) {
        #pragma unroll
        for (int it = 0; it < 2; ++it) {
            int idx = tid + it * 256;
            int arow = idx >> 2, ach = idx & 3;
            *(float4*)&As[buf][arow * SA_STRIDE + ach * 4] =
                make_float4(f2tff(pa[it].x), f2tff(pa[it].y), f2tff(pa[it].z), f2tff(pa[it].w));
            int krow = idx >> 5, nch = idx & 31;
            float* bp = &Bs[buf][0];
            bp[(nch * 4 + 0) * SA_STRIDE + krow] = f2tff(pb[it].x);
            bp[(nch * 4 + 1) * SA_STRIDE + krow] = f2tff(pb[it].y);
            bp[(nch * 4 + 2) * SA_STRIDE + krow] = f2tff(pb[it].z);
            bp[(nch * 4 + 3) * SA_STRIDE + krow] = f2tff(pb[it].w);
        }
    };

    int lrow = lane & 7;
    int lbit3 = (lane >> 3) & 1;
    int lbit4 = lane >> 4;

    int nt = K / 16;
    loadT(0);
    storeT(0);
    __syncthreads();

    #pragma unroll 1
    for (int kt = 0; kt < nt; ++kt) {
        int buf = kt & 1;
        if (kt + 1 < nt) loadT(kt + 1);

        uint32_t as_base = (uint32_t)__cvta_generic_to_shared(&As[buf][0]);
        uint32_t bs_base = (uint32_t)__cvta_generic_to_shared(&Bs[buf][0]);

        #pragma unroll
        for (int ks = 0; ks < 2; ++ks) {
            uint32_t a[4][4], b[2][4];
            #pragma unroll
            for (int mi = 0; mi < 4; ++mi) {
                int r = wm * 64 + mi * 16 + lbit3 * 8 + lrow;
                int ch = ks * 2 + lbit4;
                LDSM4(a[mi][0], a[mi][1], a[mi][2], a[mi][3],
                      as_base + (uint32_t)(r * SA_STRIDE + ch * 4) * 4u);
            }
            #pragma unroll
            for (int pi = 0; pi < 2; ++pi) {
                int r = wn * 32 + pi * 16 + lbit4 * 8 + lrow;
                int ch = ks * 2 + lbit3;
                LDSM4(b[pi][0], b[pi][1], b[pi][2], b[pi][3],
                      bs_base + (uint32_t)(r * SA_STRIDE + ch * 4) * 4u);
            }
            #pragma unroll
            for (int mi = 0; mi < 4; ++mi)
                #pragma unroll
                for (int ni = 0; ni < 4; ++ni) {
                    uint32_t b0 = b[ni >> 1][(ni & 1) * 2];
                    uint32_t b1 = b[ni >> 1][(ni & 1) * 2 + 1];
                    MMA_TF32(acc[mi][ni][0], acc[mi][ni][1], acc[mi][ni][2], acc[mi][ni][3],
                             a[mi][0], a[mi][1], a[mi][2], a[mi][3], b0, b1);
                }
        }
        if (kt + 1 < nt) storeT(buf ^ 1);
        __syncthreads();
    }

    // Epilogue: c0,c1 -> (row, 2c..2c+1); c2,c3 -> (row+8, same cols)
    int cm = blockIdx.y * 128 + wm * 64;
    int cn = blockIdx.x * 128 + wn * 32;
    int er = lane >> 2;
    int ec = (lane & 3) * 2;
    #pragma unroll
    for (int ni = 0; ni < 4; ++ni) {
        int col = cn + ni * 8 + ec;
        float b0 = bias ? bias[col] : 0.f;
        float b1 = bias ? bias[col + 1] : 0.f;
        #pragma unroll
        for (int mi = 0; mi < 4; ++mi) {
            int row = cm + mi * 16 + er;
            *(float2*)(Cm + (size_t)row * ldc + col) =
                make_float2(acc[mi][ni][0] + b0, acc[mi][ni][1] + b1);
            *(float2*)(Cm + (size_t)(row + 8) * ldc + col) =
                make_float2(acc[mi][ni][2] + b0, acc[mi][ni][3] + b1);
        }
    }
}

// ---------------------------------------------------------------------------
// 3) Scores + softmax (fp32 inputs from fp32 qk GEMM)
// ---------------------------------------------------------------------------
__global__ void attn_kernel(const float* __restrict__ qk, float* __restrict__ attn) {
    __shared__ float qs[N_][HD_];
    __shared__ float ks[N_][HD_];
    int b = blockIdx.x >> 4, h = blockIdx.x & 15;
    for (int i = threadIdx.x; i < N_ * HD_; i += 128) {
        int n = i >> 6, d = i & 63;
        const float* base = qk + ((size_t)(b * N_ + n)) * (2 * C_) + h * HD_ + d;
        qs[n][d] = base[0];
        ks[n][d] = base[C_];
    }
    __syncthreads();
    int n = threadIdx.x;
    if (n < N_) {
        float* row = attn + ((size_t)blockIdx.x * N_ + n) * N_;
        float mx = -1e30f;
        for (int m = 0; m < N_; ++m) {
            float dot = 0.f;
            #pragma unroll
            for (int d = 0; d < HD_; ++d) dot += qs[n][d] * ks[m][d];
            dot *= 0.125f;
            row[m] = dot;
            mx = fmaxf(mx, dot);
        }
        float sum = 0.f;
        for (int m = 0; m < N_; ++m) { float e = __expf(row[m] - mx); row[m] = e; sum += e; }
        float inv = 1.f / sum;
        for (int m = 0; m < N_; ++m) row[m] *= inv;
    }
}

// ---------------------------------------------------------------------------
// 5) Attention apply: out[b,n,p,c] = sum_m attn[b,h(c),n,m] * v[b,m,p,c]
// ---------------------------------------------------------------------------
__global__ void __launch_bounds__(256) apply_kernel(
    const float* __restrict__ v, const float* __restrict__ attn, float* __restrict__ out)
{
    __shared__ float vs[N_][HD_];
    __shared__ float as[48][N_ + 1];
    int bph = blockIdx.x;
    int h = bph & 15;
    int p = (bph >> 4) & 63;
    int b = bph >> 10;
    int n0 = blockIdx.y * 48;

    const float* vbase = v + ((size_t)b * N_ * P_ + p) * C_ + h * HD_;
    for (int i = threadIdx.x; i < N_ * (HD_ / 4); i += 256) {
        int m = i >> 4, c4 = i & 15;
        *(float4*)&vs[m][c4 * 4] = *(const float4*)(vbase + (size_t)m * P_ * C_ + c4 * 4);
    }
    const float* abase = attn + ((size_t)(b * H_ + h) * N_ + n0) * N_;
    for (int i = threadIdx.x; i < 48 * N_; i += 256) {
        int n = i / N_, m = i - n * N_;
        as[n][m] = abase[(size_t)n * N_ + m];
    }
    __syncthreads();

    int tx = threadIdx.x & 15, ty = threadIdx.x >> 4;
    float acc[3][4] = {};
    for (int m = 0; m < N_; ++m) {
        float4 vv = *(const float4*)&vs[m][tx * 4];
        #pragma unroll
        for (int i = 0; i < 3; ++i) {
            float a = as[ty * 3 + i][m];
            acc[i][0] += a * vv.x; acc[i][1] += a * vv.y;
            acc[i][2] += a * vv.z; acc[i][3] += a * vv.w;
        }
    }
    float* obase = out + ((size_t)b * N_ * P_ + p) * C_ + h * HD_ + tx * 4;
    #pragma unroll
    for (int i = 0; i < 3; ++i) {
        int n = n0 + ty * 3 + i;
        *(float4*)(obase + (size_t)n * P_ * C_) =
            make_float4(acc[i][0], acc[i][1], acc[i][2], acc[i][3]);
    }
}

// ---------------------------------------------------------------------------
extern "C" void kernel_launch(void* const* d_in, const int* in_sizes, int n_in,
                              void* d_out, int out_size)
{
    const float* x     = (const float*)d_in[0];
    const float* Wqkv  = (const float*)d_in[1];
    const float* Wproj = (const float*)d_in[2];
    const float* bproj = (const float*)d_in[3];
    float* out = (float*)d_out;

    float *xbar, *qkbuf, *attnbuf, *vbuf, *obuf;
    cudaGetSymbolAddress((void**)&xbar,    g_xbar);
    cudaGetSymbolAddress((void**)&qkbuf,   g_qk);
    cudaGetSymbolAddress((void**)&attnbuf, g_attn);
    cudaGetSymbolAddress((void**)&vbuf,    g_v);
    cudaGetSymbolAddress((void**)&obuf,    g_o);

    // 1) pool
    pool_kernel<<<B_ * N_, 256>>>(x, xbar);
    // 2) q,k = xbar @ W_qkv[:, 0:2048]  (fp32 for softmax precision)
    sgemm_kernel<<<dim3(2048 / BN, 384 / BM), 256>>>(
        xbar, Wqkv, qkbuf, 384, 2048, 1024, C_, 3 * C_, 2 * C_);
    // 3) scores + softmax
    attn_kernel<<<B_ * H_, 128>>>(qkbuf, attnbuf);
    // 4) v = x @ W_qkv[:, 2048:3072]  (tf32 tensor cores)
    tf32_gemm<<<dim3(C_ / 128, M_ROWS / 128), 256>>>(
        x, Wqkv + 2 * C_, vbuf, nullptr, M_ROWS, C_, C_, C_, 3 * C_, C_);
    // 5) attention apply
    apply_kernel<<<dim3(B_ * P_ * H_, 2), 256>>>(vbuf, attnbuf, obuf);
    // 6) y = o @ W_proj + b_proj  (tf32 tensor cores)
    tf32_gemm<<<dim3(C_ / 128, M_ROWS / 128), 256>>>(
        obuf, Wproj, out, bproj, M_ROWS, C_, C_, C_, C_, C_);
}

// round 4
// speedup vs baseline: 2.3165x; 1.4714x over previous
#include <cuda_runtime.h>
#include <math.h>
#include <stdint.h>

// Problem constants
#define B_ 4
#define N_ 96
#define P_ 64
#define C_ 1024
#define H_ 16
#define HD_ 64
#define M_ROWS (B_*N_*P_)   // 24576

// Scratch (device globals: allocation-free contract)
__device__ float g_xbar[B_*N_*C_];        // 384 x 1024 pooled input
__device__ float g_qk[B_*N_*2*C_];        // 384 x 2048 (q | k)
__device__ float g_attn[B_*H_*N_*N_];     // 64 x 96 x 96
__device__ float g_v[M_ROWS*C_];          // 24576 x 1024  (x @ W_v)
__device__ float g_o[M_ROWS*C_];          // 24576 x 1024  (attn-applied)

// ---------------------------------------------------------------------------
// 1) Mean-pool x over patches
// ---------------------------------------------------------------------------
__global__ void pool_kernel(const float* __restrict__ x, float* __restrict__ xbar) {
    int bn = blockIdx.x;
    const float* xp = x + (size_t)bn * P_ * C_;
    for (int c = threadIdx.x; c < C_; c += 256) {
        float s = 0.f;
        #pragma unroll 8
        for (int p = 0; p < P_; ++p) s += xp[(size_t)p * C_ + c];
        xbar[(size_t)bn * C_ + c] = s * (1.0f / 64.0f);
    }
}

// ---------------------------------------------------------------------------
// fp32 SIMT GEMM (kept for the small, precision-sensitive q/k projection)
// ---------------------------------------------------------------------------
#define BM 128
#define BN 128
#define BK 8
__global__ void __launch_bounds__(256) sgemm_kernel(
    const float* __restrict__ A, const float* __restrict__ Bm,
    float* __restrict__ Cm, int M, int N, int K, int lda, int ldb, int ldc)
{
    __shared__ float As[BK][BM + 4];
    __shared__ float Bs[BK][BN];
    int tid = threadIdx.x;
    const float* Ab = A + (size_t)blockIdx.y * BM * lda;
    const float* Bb = Bm + (size_t)blockIdx.x * BN;
    int arow = tid >> 1, acol = (tid & 1) * 4;
    int brow = tid >> 5, bcol = (tid & 31) * 4;
    int ty = tid >> 4, tx = tid & 15;
    float acc[8][8];
    #pragma unroll
    for (int i = 0; i < 8; ++i)
        #pragma unroll
        for (int j = 0; j < 8; ++j) acc[i][j] = 0.f;
    for (int k0 = 0; k0 < K; k0 += BK) {
        float4 av = *(const float4*)(Ab + (size_t)arow * lda + k0 + acol);
        As[acol + 0][arow] = av.x; As[acol + 1][arow] = av.y;
        As[acol + 2][arow] = av.z; As[acol + 3][arow] = av.w;
        float4 bv = *(const float4*)(Bb + (size_t)(k0 + brow) * ldb + bcol);
        *(float4*)&Bs[brow][bcol] = bv;
        __syncthreads();
        #pragma unroll
        for (int k = 0; k < BK; ++k) {
            float4 a0 = *(const float4*)&As[k][ty * 8];
            float4 a1 = *(const float4*)&As[k][ty * 8 + 4];
            float4 b0 = *(const float4*)&Bs[k][tx * 8];
            float4 b1 = *(const float4*)&Bs[k][tx * 8 + 4];
            float a[8] = {a0.x,a0.y,a0.z,a0.w,a1.x,a1.y,a1.z,a1.w};
            float b[8] = {b0.x,b0.y,b0.z,b0.w,b1.x,b1.y,b1.z,b1.w};
            #pragma unroll
            for (int i = 0; i < 8; ++i)
                #pragma unroll
                for (int j = 0; j < 8; ++j) acc[i][j] += a[i] * b[j];
        }
        __syncthreads();
    }
    int row0 = blockIdx.y * BM + ty * 8;
    int col0 = blockIdx.x * BN + tx * 8;
    #pragma unroll
    for (int i = 0; i < 8; ++i) {
        float* cp = Cm + (size_t)(row0 + i) * ldc + col0;
        *(float4*)cp       = make_float4(acc[i][0], acc[i][1], acc[i][2], acc[i][3]);
        *(float4*)(cp + 4) = make_float4(acc[i][4], acc[i][5], acc[i][6], acc[i][7]);
    }
}

// ---------------------------------------------------------------------------
// TF32 tensor-core GEMM v2: C = A[M,K] @ B[K,N] (+bias), tiles 128x128x16
// 8 warps: 2 (M) x 4 (N); warp tile 64x32; mma.sync.m16n8k8.tf32
// A smem [m][k] stride 20 (ldmatrix); B smem [k][n] stride 136 (direct LDS,
// conflict-free for both store and fragment load).
// ---------------------------------------------------------------------------
__device__ __forceinline__ uint32_t f2tf(float f) {
    uint32_t r; asm("cvt.rna.tf32.f32 %0, %1;" : "=r"(r) : "f"(f)); return r;
}
__device__ __forceinline__ float f2tff(float f) { return __uint_as_float(f2tf(f)); }

#define LDSM4(R0,R1,R2,R3,ADDR) \
    asm volatile("ldmatrix.sync.aligned.m8n8.x4.shared.b16 {%0,%1,%2,%3}, [%4];" \
        : "=r"(R0),"=r"(R1),"=r"(R2),"=r"(R3) : "r"(ADDR))

#define MMA_TF32(C0,C1,C2,C3,A0,A1,A2,A3,B0,B1) \
    asm volatile("mma.sync.aligned.m16n8k8.row.col.f32.tf32.tf32.f32 " \
        "{%0,%1,%2,%3}, {%4,%5,%6,%7}, {%8,%9}, {%0,%1,%2,%3};" \
        : "+f"(C0),"+f"(C1),"+f"(C2),"+f"(C3) \
        : "r"(A0),"r"(A1),"r"(A2),"r"(A3),"r"(B0),"r"(B1))

#define SA_STRIDE 20    // A: [m][k], 8 rows x stride-20 spans all banks for ldmatrix
#define SB_STRIDE 136   // B: [k][n]; fragment banks (lane&3)*8+(lane>>2) all distinct

__global__ void __launch_bounds__(256) tf32_gemm(
    const float* __restrict__ A, const float* __restrict__ Bm,
    float* __restrict__ Cm, const float* __restrict__ bias,
    int M, int N, int K, int lda, int ldb, int ldc)
{
    __shared__ __align__(16) float As[2][128 * SA_STRIDE];   // 20 KB
    __shared__ __align__(16) float Bs[2][16 * SB_STRIDE];    // 17 KB

    int tid = threadIdx.x;
    int lane = tid & 31, warp = tid >> 5;
    int wm = warp & 1, wn = warp >> 1;

    const float* Ab = A + (size_t)blockIdx.y * 128 * lda;
    const float* Bb = Bm + (size_t)blockIdx.x * 128;

    float acc[4][4][4];
    #pragma unroll
    for (int i = 0; i < 4; ++i)
        #pragma unroll
        for (int j = 0; j < 4; ++j)
            #pragma unroll
            for (int r = 0; r < 4; ++r) acc[i][j][r] = 0.f;

    float4 pa[2], pb[2];
    auto loadT = [&](int kt) {
        #pragma unroll
        for (int it = 0; it < 2; ++it) {
            int idx = tid + it * 256;
            int arow = idx >> 2, ach = idx & 3;
            pa[it] = *(const float4*)(Ab + (size_t)arow * lda + kt * 16 + ach * 4);
            int krow = idx >> 5, nch = idx & 31;
            pb[it] = *(const float4*)(Bb + (size_t)(kt * 16 + krow) * ldb + nch * 4);
        }
    };
    auto storeT = [&](int buf) {
        #pragma unroll
        for (int it = 0; it < 2; ++it) {
            int idx = tid + it * 256;
            int arow = idx >> 2, ach = idx & 3;
            *(float4*)&As[buf][arow * SA_STRIDE + ach * 4] =
                make_float4(f2tff(pa[it].x), f2tff(pa[it].y), f2tff(pa[it].z), f2tff(pa[it].w));
            int krow = idx >> 5, nch = idx & 31;
            *(float4*)&Bs[buf][krow * SB_STRIDE + nch * 4] =
                make_float4(f2tff(pb[it].x), f2tff(pb[it].y), f2tff(pb[it].z), f2tff(pb[it].w));
        }
    };

    int lrow = lane & 7;
    int lbit3 = (lane >> 3) & 1;
    int lbit4 = lane >> 4;
    int bk = lane & 3;            // B fragment k-offset within 8
    int bn = lane >> 2;           // B fragment n-offset within 8

    int nt = K / 16;
    loadT(0);
    storeT(0);
    __syncthreads();

    #pragma unroll 1
    for (int kt = 0; kt < nt; ++kt) {
        int buf = kt & 1;
        if (kt + 1 < nt) loadT(kt + 1);

        uint32_t as_base = (uint32_t)__cvta_generic_to_shared(&As[buf][0]);
        const float* bsp = &Bs[buf][0];

        #pragma unroll
        for (int ks = 0; ks < 2; ++ks) {
            uint32_t a[4][4];
            #pragma unroll
            for (int mi = 0; mi < 4; ++mi) {
                int r = wm * 64 + mi * 16 + lbit3 * 8 + lrow;
                int ch = ks * 2 + lbit4;
                LDSM4(a[mi][0], a[mi][1], a[mi][2], a[mi][3],
                      as_base + (uint32_t)(r * SA_STRIDE + ch * 4) * 4u);
            }
            uint32_t b0[4], b1[4];
            #pragma unroll
            for (int ni = 0; ni < 4; ++ni) {
                int n0 = wn * 32 + ni * 8 + bn;
                int k0 = ks * 8 + bk;
                b0[ni] = __float_as_uint(bsp[k0 * SB_STRIDE + n0]);
                b1[ni] = __float_as_uint(bsp[(k0 + 4) * SB_STRIDE + n0]);
            }
            #pragma unroll
            for (int mi = 0; mi < 4; ++mi)
                #pragma unroll
                for (int ni = 0; ni < 4; ++ni)
                    MMA_TF32(acc[mi][ni][0], acc[mi][ni][1], acc[mi][ni][2], acc[mi][ni][3],
                             a[mi][0], a[mi][1], a[mi][2], a[mi][3], b0[ni], b1[ni]);
        }
        if (kt + 1 < nt) storeT(buf ^ 1);
        __syncthreads();
    }

    // Epilogue: c0,c1 -> (row, 2c..2c+1); c2,c3 -> (row+8, same cols)
    int cm = blockIdx.y * 128 + wm * 64;
    int cn = blockIdx.x * 128 + wn * 32;
    int er = lane >> 2;
    int ec = (lane & 3) * 2;
    #pragma unroll
    for (int ni = 0; ni < 4; ++ni) {
        int col = cn + ni * 8 + ec;
        float bb0 = bias ? bias[col] : 0.f;
        float bb1 = bias ? bias[col + 1] : 0.f;
        #pragma unroll
        for (int mi = 0; mi < 4; ++mi) {
            int row = cm + mi * 16 + er;
            *(float2*)(Cm + (size_t)row * ldc + col) =
                make_float2(acc[mi][ni][0] + bb0, acc[mi][ni][1] + bb1);
            *(float2*)(Cm + (size_t)(row + 8) * ldc + col) =
                make_float2(acc[mi][ni][2] + bb0, acc[mi][ni][3] + bb1);
        }
    }
}

// ---------------------------------------------------------------------------
// 3) Scores + softmax (fp32 inputs from fp32 qk GEMM)
// ---------------------------------------------------------------------------
__global__ void attn_kernel(const float* __restrict__ qk, float* __restrict__ attn) {
    __shared__ float qs[N_][HD_];
    __shared__ float ks[N_][HD_];
    int b = blockIdx.x >> 4, h = blockIdx.x & 15;
    for (int i = threadIdx.x; i < N_ * HD_; i += 128) {
        int n = i >> 6, d = i & 63;
        const float* base = qk + ((size_t)(b * N_ + n)) * (2 * C_) + h * HD_ + d;
        qs[n][d] = base[0];
        ks[n][d] = base[C_];
    }
    __syncthreads();
    int n = threadIdx.x;
    if (n < N_) {
        float* row = attn + ((size_t)blockIdx.x * N_ + n) * N_;
        float mx = -1e30f;
        for (int m = 0; m < N_; ++m) {
            float dot = 0.f;
            #pragma unroll
            for (int d = 0; d < HD_; ++d) dot += qs[n][d] * ks[m][d];
            dot *= 0.125f;
            row[m] = dot;
            mx = fmaxf(mx, dot);
        }
        float sum = 0.f;
        for (int m = 0; m < N_; ++m) { float e = __expf(row[m] - mx); row[m] = e; sum += e; }
        float inv = 1.f / sum;
        for (int m = 0; m < N_; ++m) row[m] *= inv;
    }
}

// ---------------------------------------------------------------------------
// 5) Attention apply: out[b,n,p,c] = sum_m attn[b,h(c),n,m] * v[b,m,p,c]
// ---------------------------------------------------------------------------
__global__ void __launch_bounds__(256) apply_kernel(
    const float* __restrict__ v, const float* __restrict__ attn, float* __restrict__ out)
{
    __shared__ float vs[N_][HD_];
    __shared__ float as[48][N_ + 1];
    int bph = blockIdx.x;
    int h = bph & 15;
    int p = (bph >> 4) & 63;
    int b = bph >> 10;
    int n0 = blockIdx.y * 48;

    const float* vbase = v + ((size_t)b * N_ * P_ + p) * C_ + h * HD_;
    for (int i = threadIdx.x; i < N_ * (HD_ / 4); i += 256) {
        int m = i >> 4, c4 = i & 15;
        *(float4*)&vs[m][c4 * 4] = *(const float4*)(vbase + (size_t)m * P_ * C_ + c4 * 4);
    }
    const float* abase = attn + ((size_t)(b * H_ + h) * N_ + n0) * N_;
    for (int i = threadIdx.x; i < 48 * N_; i += 256) {
        int n = i / N_, m = i - n * N_;
        as[n][m] = abase[(size_t)n * N_ + m];
    }
    __syncthreads();

    int tx = threadIdx.x & 15, ty = threadIdx.x >> 4;
    float acc[3][4] = {};
    for (int m = 0; m < N_; ++m) {
        float4 vv = *(const float4*)&vs[m][tx * 4];
        #pragma unroll
        for (int i = 0; i < 3; ++i) {
            float a = as[ty * 3 + i][m];
            acc[i][0] += a * vv.x; acc[i][1] += a * vv.y;
            acc[i][2] += a * vv.z; acc[i][3] += a * vv.w;
        }
    }
    float* obase = out + ((size_t)b * N_ * P_ + p) * C_ + h * HD_ + tx * 4;
    #pragma unroll
    for (int i = 0; i < 3; ++i) {
        int n = n0 + ty * 3 + i;
        *(float4*)(obase + (size_t)n * P_ * C_) =
            make_float4(acc[i][0], acc[i][1], acc[i][2], acc[i][3]);
    }
}

// ---------------------------------------------------------------------------
extern "C" void kernel_launch(void* const* d_in, const int* in_sizes, int n_in,
                              void* d_out, int out_size)
{
    const float* x     = (const float*)d_in[0];
    const float* Wqkv  = (const float*)d_in[1];
    const float* Wproj = (const float*)d_in[2];
    const float* bproj = (const float*)d_in[3];
    float* out = (float*)d_out;

    float *xbar, *qkbuf, *attnbuf, *vbuf, *obuf;
    cudaGetSymbolAddress((void**)&xbar,    g_xbar);
    cudaGetSymbolAddress((void**)&qkbuf,   g_qk);
    cudaGetSymbolAddress((void**)&attnbuf, g_attn);
    cudaGetSymbolAddress((void**)&vbuf,    g_v);
    cudaGetSymbolAddress((void**)&obuf,    g_o);

    // 1) pool
    pool_kernel<<<B_ * N_, 256>>>(x, xbar);
    // 2) q,k = xbar @ W_qkv[:, 0:2048]  (fp32 for softmax precision)
    sgemm_kernel<<<dim3(2048 / BN, 384 / BM), 256>>>(
        xbar, Wqkv, qkbuf, 384, 2048, 1024, C_, 3 * C_, 2 * C_);
    // 3) scores + softmax
    attn_kernel<<<B_ * H_, 128>>>(qkbuf, attnbuf);
    // 4) v = x @ W_qkv[:, 2048:3072]  (tf32 tensor cores)
    tf32_gemm<<<dim3(C_ / 128, M_ROWS / 128), 256>>>(
        x, Wqkv + 2 * C_, vbuf, nullptr, M_ROWS, C_, C_, C_, 3 * C_, C_);
    // 5) attention apply
    apply_kernel<<<dim3(B_ * P_ * H_, 2), 256>>>(vbuf, attnbuf, obuf);
    // 6) y = o @ W_proj + b_proj  (tf32 tensor cores)
    tf32_gemm<<<dim3(C_ / 128, M_ROWS / 128), 256>>>(
        obuf, Wproj, out, bproj, M_ROWS, C_, C_, C_, C_, C_);
}

// round 6
// speedup vs baseline: 2.6246x; 1.1330x over previous
#include <cuda_runtime.h>
#include <math.h>
#include <stdint.h>

// Problem constants
#define B_ 4
#define N_ 96
#define P_ 64
#define C_ 1024
#define H_ 16
#define HD_ 64
#define M_ROWS (B_*N_*P_)   // 24576

// Scratch (device globals: allocation-free contract)
__device__ float g_xbar[B_*N_*C_];        // pooled input, tf32-rounded
__device__ float g_qk[B_*N_*2*C_];        // q|k projections
__device__ float g_attn[B_*H_*N_*N_];     // softmax weights
__device__ float g_v[M_ROWS*C_];          // x @ W_v
__device__ float g_o[M_ROWS*C_];          // attn-applied (tf32-rounded)
__device__ float g_xt[M_ROWS*C_];         // x, tf32-rounded
__device__ float g_wqkt[2*C_*C_];         // W_qk^T [n][k], tf32-rounded
__device__ float g_wvt[C_*C_];            // W_v^T
__device__ float g_wpt[C_*C_];            // W_proj^T

__device__ __forceinline__ float f2tff(float f) {
    uint32_t r; asm("cvt.rna.tf32.f32 %0, %1;" : "=r"(r) : "f"(f));
    return __uint_as_float(r);
}

#define LDSM4(R0,R1,R2,R3,ADDR) \
    asm volatile("ldmatrix.sync.aligned.m8n8.x4.shared.b16 {%0,%1,%2,%3}, [%4];" \
        : "=r"(R0),"=r"(R1),"=r"(R2),"=r"(R3) : "r"(ADDR))

#define MMA_TF32(C0,C1,C2,C3,A0,A1,A2,A3,B0,B1) \
    asm volatile("mma.sync.aligned.m16n8k8.row.col.f32.tf32.tf32.f32 " \
        "{%0,%1,%2,%3}, {%4,%5,%6,%7}, {%8,%9}, {%0,%1,%2,%3};" \
        : "+f"(C0),"+f"(C1),"+f"(C2),"+f"(C3) \
        : "r"(A0),"r"(A1),"r"(A2),"r"(A3),"r"(B0),"r"(B1))

#define CP16(DST, SRC) \
    asm volatile("cp.async.cg.shared.global [%0], [%1], 16;" :: "r"(DST), "l"(SRC) : "memory")
#define CP_COMMIT() asm volatile("cp.async.commit_group;" ::: "memory")
#define CP_WAIT1()  asm volatile("cp.async.wait_group 1;" ::: "memory")

// ---------------------------------------------------------------------------
// TF32 tensor-core GEMM v3: C[.,*] = A[M,K] @ Bt[Ncols,K]^T (+bias)
// A row-major [m][k] (pre-tf32); Bt row-major [n][k] (pre-transposed, pre-tf32).
// CTA tile 128x128, KTILE=16, 3-stage cp.async pipeline, stride-20 smem rows,
// all fragments via ldmatrix (conflict-free). 8 warps: 2(M) x 4(N), 64x32 each.
// ---------------------------------------------------------------------------
#define SROW 20                       // floats per smem row (conflict-free)
#define TILEB  (128 * SROW * 4)       // 10240 B per matrix tile
#define STAGEB (2 * TILEB)            // 20480 B per stage (A + B)
#define NSTAGE 3
#define TC_SMEM (NSTAGE * STAGEB)     // 61440 B

__global__ void __launch_bounds__(256) tc_gemm(
    const float* __restrict__ A, const float* __restrict__ Bt,
    float* __restrict__ Cm, const float* __restrict__ bias,
    int K, int lda, int ldb, int ldc)
{
    extern __shared__ float smem[];
    uint32_t smem_base = (uint32_t)__cvta_generic_to_shared(smem);
    int tid = threadIdx.x;
    int lane = tid & 31, warp = tid >> 5;
    int wm = warp & 1, wn = warp >> 1;

    const float* Ab = A + (size_t)blockIdx.y * 128 * lda;
    const float* Bb = Bt + (size_t)blockIdx.x * 128 * ldb;

    float acc[4][4][4];
    #pragma unroll
    for (int i = 0; i < 4; ++i)
        #pragma unroll
        for (int j = 0; j < 4; ++j)
            #pragma unroll
            for (int r = 0; r < 4; ++r) acc[i][j][r] = 0.f;

    auto load_stage = [&](int s, int kt) {
        uint32_t sa = smem_base + s * STAGEB;
        uint32_t sb = sa + TILEB;
        #pragma unroll
        for (int it = 0; it < 2; ++it) {
            int j = tid + it * 256;
            int r = j >> 2, c = j & 3;
            uint32_t so = (uint32_t)(r * SROW + c * 4) * 4u;
            CP16(sa + so, Ab + (size_t)r * lda + kt * 16 + c * 4);
            CP16(sb + so, Bb + (size_t)r * ldb + kt * 16 + c * 4);
        }
    };

    int nt = K / 16;
    load_stage(0, 0); CP_COMMIT();
    load_stage(1, 1); CP_COMMIT();

    int lrow = lane & 7;
    int lb3 = (lane >> 3) & 1;
    int lb4 = lane >> 4;

    #pragma unroll 1
    for (int kt = 0; kt < nt; ++kt) {
        CP_WAIT1();          // stage kt resident
        __syncthreads();     // visible to all warps; stage kt-1 fully consumed
        if (kt + 2 < nt) load_stage((kt + 2) % NSTAGE, kt + 2);
        CP_COMMIT();         // empty group near tail keeps accounting uniform

        uint32_t sa = smem_base + (kt % NSTAGE) * STAGEB;
        uint32_t sb = sa + TILEB;

        #pragma unroll
        for (int ks = 0; ks < 2; ++ks) {
            uint32_t a[4][4], b[2][4];
            #pragma unroll
            for (int mi = 0; mi < 4; ++mi) {
                int r = wm * 64 + mi * 16 + lb3 * 8 + lrow;
                int ch = ks * 2 + lb4;
                LDSM4(a[mi][0], a[mi][1], a[mi][2], a[mi][3],
                      sa + (uint32_t)(r * SROW + ch * 4) * 4u);
            }
            #pragma unroll
            for (int pi = 0; pi < 2; ++pi) {
                int r = wn * 32 + pi * 16 + lb4 * 8 + lrow;
                int ch = ks * 2 + lb3;
                LDSM4(b[pi][0], b[pi][1], b[pi][2], b[pi][3],
                      sb + (uint32_t)(r * SROW + ch * 4) * 4u);
            }
            #pragma unroll
            for (int mi = 0; mi < 4; ++mi)
                #pragma unroll
                for (int ni = 0; ni < 4; ++ni)
                    MMA_TF32(acc[mi][ni][0], acc[mi][ni][1], acc[mi][ni][2], acc[mi][ni][3],
                             a[mi][0], a[mi][1], a[mi][2], a[mi][3],
                             b[ni >> 1][(ni & 1) * 2], b[ni >> 1][(ni & 1) * 2 + 1]);
        }
    }

    // Epilogue: c0,c1 -> (row, 2c..2c+1); c2,c3 -> (row+8)
    int cm = blockIdx.y * 128 + wm * 64;
    int cn = blockIdx.x * 128 + wn * 32;
    int er = lane >> 2;
    int ec = (lane & 3) * 2;
    #pragma unroll
    for (int ni = 0; ni < 4; ++ni) {
        int col = cn + ni * 8 + ec;
        float bb0 = bias ? bias[col] : 0.f;
        float bb1 = bias ? bias[col + 1] : 0.f;
        #pragma unroll
        for (int mi = 0; mi < 4; ++mi) {
            int row = cm + mi * 16 + er;
            *(float2*)(Cm + (size_t)row * ldc + col) =
                make_float2(acc[mi][ni][0] + bb0, acc[mi][ni][1] + bb1);
            *(float2*)(Cm + (size_t)(row + 8) * ldc + col) =
                make_float2(acc[mi][ni][2] + bb0, acc[mi][ni][3] + bb1);
        }
    }
}

// ---------------------------------------------------------------------------
// Weight transpose + tf32 rounding: Wt[n][k] = cvt(W[k][n]); output ld = 1024
// ---------------------------------------------------------------------------
__global__ void wtrans_kernel(const float* __restrict__ W, float* __restrict__ Wt, int ldw) {
    __shared__ float t[32][33];
    int n0 = blockIdx.x * 32, k0 = blockIdx.y * 32;
    int tx = threadIdx.x, ty = threadIdx.y;   // 32 x 8
    #pragma unroll
    for (int i = 0; i < 32; i += 8)
        t[ty + i][tx] = W[(size_t)(k0 + ty + i) * ldw + n0 + tx];
    __syncthreads();
    #pragma unroll
    for (int i = 0; i < 32; i += 8)
        Wt[(size_t)(n0 + ty + i) * C_ + k0 + tx] = f2tff(t[tx][ty + i]);
}

// ---------------------------------------------------------------------------
// tf32 rounding pass for x
// ---------------------------------------------------------------------------
__global__ void cvt_kernel(const float* __restrict__ in, float* __restrict__ out) {
    size_t i = ((size_t)blockIdx.x * 256 + threadIdx.x) * 4;
    float4 v = *(const float4*)(in + i);
    *(float4*)(out + i) = make_float4(f2tff(v.x), f2tff(v.y), f2tff(v.z), f2tff(v.w));
}

// ---------------------------------------------------------------------------
// 1) Mean-pool x over patches (tf32-rounded output; feeds qk GEMM)
// ---------------------------------------------------------------------------
__global__ void pool_kernel(const float* __restrict__ x, float* __restrict__ xbar) {
    int bn = blockIdx.x;
    const float* xp = x + (size_t)bn * P_ * C_;
    for (int c = threadIdx.x; c < C_; c += 256) {
        float s = 0.f;
        #pragma unroll 8
        for (int p = 0; p < P_; ++p) s += xp[(size_t)p * C_ + c];
        xbar[(size_t)bn * C_ + c] = f2tff(s * (1.0f / 64.0f));
    }
}

// ---------------------------------------------------------------------------
// 3) Scores + softmax
// ---------------------------------------------------------------------------
__global__ void attn_kernel(const float* __restrict__ qk, float* __restrict__ attn) {
    __shared__ float qs[N_][HD_];
    __shared__ float ks[N_][HD_];
    int b = blockIdx.x >> 4, h = blockIdx.x & 15;
    for (int i = threadIdx.x; i < N_ * HD_; i += 128) {
        int n = i >> 6, d = i & 63;
        const float* base = qk + ((size_t)(b * N_ + n)) * (2 * C_) + h * HD_ + d;
        qs[n][d] = base[0];
        ks[n][d] = base[C_];
    }
    __syncthreads();
    int n = threadIdx.x;
    if (n < N_) {
        float* row = attn + ((size_t)blockIdx.x * N_ + n) * N_;
        float mx = -1e30f;
        for (int m = 0; m < N_; ++m) {
            float dot = 0.f;
            #pragma unroll
            for (int d = 0; d < HD_; ++d) dot += qs[n][d] * ks[m][d];
            dot *= 0.125f;
            row[m] = dot;
            mx = fmaxf(mx, dot);
        }
        float sum = 0.f;
        for (int m = 0; m < N_; ++m) { float e = __expf(row[m] - mx); row[m] = e; sum += e; }
        float inv = 1.f / sum;
        for (int m = 0; m < N_; ++m) row[m] *= inv;
    }
}

// ---------------------------------------------------------------------------
// 5) Attention apply (tf32-rounded output; feeds proj GEMM)
// ---------------------------------------------------------------------------
__global__ void __launch_bounds__(256) apply_kernel(
    const float* __restrict__ v, const float* __restrict__ attn, float* __restrict__ out)
{
    __shared__ float vs[N_][HD_];
    __shared__ float as[48][N_ + 1];
    int bph = blockIdx.x;
    int h = bph & 15;
    int p = (bph >> 4) & 63;
    int b = bph >> 10;
    int n0 = blockIdx.y * 48;

    const float* vbase = v + ((size_t)b * N_ * P_ + p) * C_ + h * HD_;
    for (int i = threadIdx.x; i < N_ * (HD_ / 4); i += 256) {
        int m = i >> 4, c4 = i & 15;
        *(float4*)&vs[m][c4 * 4] = *(const float4*)(vbase + (size_t)m * P_ * C_ + c4 * 4);
    }
    const float* abase = attn + ((size_t)(b * H_ + h) * N_ + n0) * N_;
    for (int i = threadIdx.x; i < 48 * N_; i += 256) {
        int n = i / N_, m = i - n * N_;
        as[n][m] = abase[(size_t)n * N_ + m];
    }
    __syncthreads();

    int tx = threadIdx.x & 15, ty = threadIdx.x >> 4;
    float acc[3][4] = {};
    for (int m = 0; m < N_; ++m) {
        float4 vv = *(const float4*)&vs[m][tx * 4];
        #pragma unroll
        for (int i = 0; i < 3; ++i) {
            float a = as[ty * 3 + i][m];
            acc[i][0] += a * vv.x; acc[i][1] += a * vv.y;
            acc[i][2] += a * vv.z; acc[i][3] += a * vv.w;
        }
    }
    float* obase = out + ((size_t)b * N_ * P_ + p) * C_ + h * HD_ + tx * 4;
    #pragma unroll
    for (int i = 0; i < 3; ++i) {
        int n = n0 + ty * 3 + i;
        *(float4*)(obase + (size_t)n * P_ * C_) =
            make_float4(f2tff(acc[i][0]), f2tff(acc[i][1]), f2tff(acc[i][2]), f2tff(acc[i][3]));
    }
}

// ---------------------------------------------------------------------------
extern "C" void kernel_launch(void* const* d_in, const int* in_sizes, int n_in,
                              void* d_out, int out_size)
{
    const float* x     = (const float*)d_in[0];
    const float* Wqkv  = (const float*)d_in[1];
    const float* Wproj = (const float*)d_in[2];
    const float* bproj = (const float*)d_in[3];
    float* out = (float*)d_out;

    float *xbar, *qkbuf, *attnbuf, *vbuf, *obuf, *xt, *wqkt, *wvt, *wpt;
    cudaGetSymbolAddress((void**)&xbar,    g_xbar);
    cudaGetSymbolAddress((void**)&qkbuf,   g_qk);
    cudaGetSymbolAddress((void**)&attnbuf, g_attn);
    cudaGetSymbolAddress((void**)&vbuf,    g_v);
    cudaGetSymbolAddress((void**)&obuf,    g_o);
    cudaGetSymbolAddress((void**)&xt,      g_xt);
    cudaGetSymbolAddress((void**)&wqkt,    g_wqkt);
    cudaGetSymbolAddress((void**)&wvt,     g_wvt);
    cudaGetSymbolAddress((void**)&wpt,     g_wpt);

    cudaFuncSetAttribute(tc_gemm, cudaFuncAttributeMaxDynamicSharedMemorySize, TC_SMEM);

    // 0) weight transposes (+tf32) and activation rounding
    wtrans_kernel<<<dim3(64, 32), dim3(32, 8)>>>(Wqkv, wqkt, 3 * C_);           // q|k cols
    wtrans_kernel<<<dim3(32, 32), dim3(32, 8)>>>(Wqkv + 2 * C_, wvt, 3 * C_);   // v cols
    wtrans_kernel<<<dim3(32, 32), dim3(32, 8)>>>(Wproj, wpt, C_);
    cvt_kernel<<<M_ROWS, 256>>>(x, xt);
    // 1) pool (tf32-rounded)
    pool_kernel<<<B_ * N_, 256>>>(x, xbar);
    // 2) q,k = xbar @ W_qk  (tensor cores)
    tc_gemm<<<dim3(16, 3), 256, TC_SMEM>>>(xbar, wqkt, qkbuf, nullptr, 1024, C_, C_, 2 * C_);
    // 3) scores + softmax
    attn_kernel<<<B_ * H_, 128>>>(qkbuf, attnbuf);
    // 4) v = x @ W_v
    tc_gemm<<<dim3(8, 192), 256, TC_SMEM>>>(xt, wvt, vbuf, nullptr, 1024, C_, C_, C_);
    // 5) attention apply (tf32-rounded)
    apply_kernel<<<dim3(B_ * P_ * H_, 2), 256>>>(vbuf, attnbuf, obuf);
    // 6) y = o @ W_proj + b
    tc_gemm<<<dim3(8, 192), 256, TC_SMEM>>>(obuf, wpt, out, bproj, 1024, C_, C_, C_);
}

// round 7
// speedup vs baseline: 2.8016x; 1.0675x over previous
#include <cuda_runtime.h>
#include <math.h>
#include <stdint.h>

// Problem constants
#define B_ 4
#define N_ 96
#define P_ 64
#define C_ 1024
#define H_ 16
#define HD_ 64
#define M_ROWS (B_*N_*P_)   // 24576

// Scratch (device globals: allocation-free contract)
__device__ float g_xbar[B_*N_*C_];        // pooled input, tf32-rounded
__device__ float g_qk[B_*N_*2*C_];        // q|k projections
__device__ float g_attn[B_*H_*N_*N_];     // softmax weights (tf32-rounded)
__device__ float g_v[M_ROWS*C_];          // x @ W_v (tf32-rounded)
__device__ float g_o[M_ROWS*C_];          // attn-applied (tf32-rounded)
__device__ float g_xt[M_ROWS*C_];         // x, tf32-rounded
__device__ float g_wqkt[2*C_*C_];         // W_qk^T [n][k], tf32-rounded
__device__ float g_wvt[C_*C_];            // W_v^T
__device__ float g_wpt[C_*C_];            // W_proj^T

__device__ __forceinline__ float f2tff(float f) {
    uint32_t r; asm("cvt.rna.tf32.f32 %0, %1;" : "=r"(r) : "f"(f));
    return __uint_as_float(r);
}

#define LDSM4(R0,R1,R2,R3,ADDR) \
    asm volatile("ldmatrix.sync.aligned.m8n8.x4.shared.b16 {%0,%1,%2,%3}, [%4];" \
        : "=r"(R0),"=r"(R1),"=r"(R2),"=r"(R3) : "r"(ADDR))

#define MMA_TF32(C0,C1,C2,C3,A0,A1,A2,A3,B0,B1) \
    asm volatile("mma.sync.aligned.m16n8k8.row.col.f32.tf32.tf32.f32 " \
        "{%0,%1,%2,%3}, {%4,%5,%6,%7}, {%8,%9}, {%0,%1,%2,%3};" \
        : "+f"(C0),"+f"(C1),"+f"(C2),"+f"(C3) \
        : "r"(A0),"r"(A1),"r"(A2),"r"(A3),"r"(B0),"r"(B1))

#define CP16(DST, SRC) \
    asm volatile("cp.async.cg.shared.global [%0], [%1], 16;" :: "r"(DST), "l"(SRC) : "memory")
#define CP_COMMIT() asm volatile("cp.async.commit_group;" ::: "memory")
#define CP_WAIT1()  asm volatile("cp.async.wait_group 1;" ::: "memory")

// ---------------------------------------------------------------------------
// TF32 tensor GEMM v4: C = A[M,K] @ Bt[N,K]^T (+bias, opt tf32-round output)
// CTA tile 128x256, warp tile 64x64 (8 warps: 2M x 4N), KTILE=16, 3-stage
// cp.async, stride-20 smem rows, all fragments via ldmatrix.
// ---------------------------------------------------------------------------
#define SROW 20
#define TILEA_B (128 * SROW * 4)            // 10240
#define TILEB_B (256 * SROW * 4)            // 20480
#define STAGEB  (TILEA_B + TILEB_B)         // 30720
#define NSTAGE 3
#define TC_SMEM (NSTAGE * STAGEB)           // 92160

__global__ void __launch_bounds__(256) tc_gemm(
    const float* __restrict__ A, const float* __restrict__ Bt,
    float* __restrict__ Cm, const float* __restrict__ bias,
    int K, int lda, int ldb, int ldc, int roundOut)
{
    extern __shared__ float smem[];
    uint32_t smem_base = (uint32_t)__cvta_generic_to_shared(smem);
    int tid = threadIdx.x;
    int lane = tid & 31, warp = tid >> 5;
    int wm = warp & 1, wn = warp >> 1;

    const float* Ab = A + (size_t)blockIdx.y * 128 * lda;
    const float* Bb = Bt + (size_t)blockIdx.x * 256 * ldb;

    float acc[4][8][4];
    #pragma unroll
    for (int i = 0; i < 4; ++i)
        #pragma unroll
        for (int j = 0; j < 8; ++j)
            #pragma unroll
            for (int r = 0; r < 4; ++r) acc[i][j][r] = 0.f;

    auto load_stage = [&](int s, int kt) {
        uint32_t sa = smem_base + s * STAGEB;
        uint32_t sb = sa + TILEA_B;
        #pragma unroll
        for (int it = 0; it < 2; ++it) {          // A: 512 chunks
            int q = tid + it * 256;
            int r = q >> 2, c = q & 3;
            CP16(sa + (uint32_t)(r * SROW + c * 4) * 4u,
                 Ab + (size_t)r * lda + kt * 16 + c * 4);
        }
        #pragma unroll
        for (int it = 0; it < 4; ++it) {          // B: 1024 chunks
            int q = tid + it * 256;
            int r = q >> 2, c = q & 3;
            CP16(sb + (uint32_t)(r * SROW + c * 4) * 4u,
                 Bb + (size_t)r * ldb + kt * 16 + c * 4);
        }
    };

    int nt = K / 16;
    load_stage(0, 0); CP_COMMIT();
    load_stage(1, 1); CP_COMMIT();

    int lrow = lane & 7;
    int lb3 = (lane >> 3) & 1;
    int lb4 = lane >> 4;

    #pragma unroll 1
    for (int kt = 0; kt < nt; ++kt) {
        CP_WAIT1();
        __syncthreads();
        if (kt + 2 < nt) load_stage((kt + 2) % NSTAGE, kt + 2);
        CP_COMMIT();

        uint32_t sa = smem_base + (kt % NSTAGE) * STAGEB;
        uint32_t sb = sa + TILEA_B;

        #pragma unroll
        for (int ks = 0; ks < 2; ++ks) {
            uint32_t a[4][4], b[4][4];
            #pragma unroll
            for (int mi = 0; mi < 4; ++mi) {
                int r = wm * 64 + mi * 16 + lb3 * 8 + lrow;
                int ch = ks * 2 + lb4;
                LDSM4(a[mi][0], a[mi][1], a[mi][2], a[mi][3],
                      sa + (uint32_t)(r * SROW + ch * 4) * 4u);
            }
            #pragma unroll
            for (int pi = 0; pi < 4; ++pi) {
                int r = wn * 64 + pi * 16 + lb4 * 8 + lrow;
                int ch = ks * 2 + lb3;
                LDSM4(b[pi][0], b[pi][1], b[pi][2], b[pi][3],
                      sb + (uint32_t)(r * SROW + ch * 4) * 4u);
            }
            #pragma unroll
            for (int mi = 0; mi < 4; ++mi)
                #pragma unroll
                for (int ni = 0; ni < 8; ++ni)
                    MMA_TF32(acc[mi][ni][0], acc[mi][ni][1], acc[mi][ni][2], acc[mi][ni][3],
                             a[mi][0], a[mi][1], a[mi][2], a[mi][3],
                             b[ni >> 1][(ni & 1) * 2], b[ni >> 1][(ni & 1) * 2 + 1]);
        }
    }

    int cm = blockIdx.y * 128 + wm * 64;
    int cn = blockIdx.x * 256 + wn * 64;
    int er = lane >> 2;
    int ec = (lane & 3) * 2;
    #pragma unroll
    for (int ni = 0; ni < 8; ++ni) {
        int col = cn + ni * 8 + ec;
        float bb0 = bias ? bias[col] : 0.f;
        float bb1 = bias ? bias[col + 1] : 0.f;
        #pragma unroll
        for (int mi = 0; mi < 4; ++mi) {
            int row = cm + mi * 16 + er;
            float v0 = acc[mi][ni][0] + bb0, v1 = acc[mi][ni][1] + bb1;
            float v2 = acc[mi][ni][2] + bb0, v3 = acc[mi][ni][3] + bb1;
            if (roundOut) { v0 = f2tff(v0); v1 = f2tff(v1); v2 = f2tff(v2); v3 = f2tff(v3); }
            *(float2*)(Cm + (size_t)row * ldc + col) = make_float2(v0, v1);
            *(float2*)(Cm + (size_t)(row + 8) * ldc + col) = make_float2(v2, v3);
        }
    }
}

// ---------------------------------------------------------------------------
// apply_tc: per (b,h) GEMM  o[n, (p,hd)] = attn[n,m] @ v[m, (p,hd)]
// CTA tile 96x128 (2 p-values x 64 hd), warp tile 48x32, K=96 (6 k-tiles).
// A [n][k] stride 20 via ldmatrix; B [k][n] stride 136 via direct LDS.
// Output tf32-rounded (feeds proj GEMM).
// ---------------------------------------------------------------------------
#define AP_AROW 20
#define AP_BROW 136
#define AP_TILEA (96 * AP_AROW * 4)     // 7680
#define AP_TILEB (16 * AP_BROW * 4)     // 8704
#define AP_STAGE (AP_TILEA + AP_TILEB)  // 16384
#define AP_SMEM  (3 * AP_STAGE)         // 49152

__global__ void __launch_bounds__(256) apply_tc(
    const float* __restrict__ v, const float* __restrict__ attn, float* __restrict__ out)
{
    extern __shared__ float smem[];
    uint32_t smem_base = (uint32_t)__cvta_generic_to_shared(smem);
    int tid = threadIdx.x;
    int lane = tid & 31, warp = tid >> 5;
    int wm = warp & 1, wn = warp >> 1;

    int bh = blockIdx.y;
    int b = bh >> 4, h = bh & 15;
    int p0 = blockIdx.x * 2;                    // col tile = 2 p x 64 hd

    const float* ab = attn + (size_t)bh * N_ * N_;
    const float* vb = v + (size_t)b * N_ * P_ * C_ + h * HD_;

    float acc[3][4][4];
    #pragma unroll
    for (int i = 0; i < 3; ++i)
        #pragma unroll
        for (int j = 0; j < 4; ++j)
            #pragma unroll
            for (int r = 0; r < 4; ++r) acc[i][j][r] = 0.f;

    auto load_stage = [&](int s, int kt) {
        uint32_t sa = smem_base + s * AP_STAGE;
        uint32_t sb = sa + AP_TILEA;
        // A: 96 rows x 16 k = 384 chunks
        {
            int q = tid;
            int r = q >> 2, c = q & 3;
            CP16(sa + (uint32_t)(r * AP_AROW + c * 4) * 4u,
                 ab + (size_t)r * N_ + kt * 16 + c * 4);
            if (tid < 128) {
                q = tid + 256; r = q >> 2; c = q & 3;
                CP16(sa + (uint32_t)(r * AP_AROW + c * 4) * 4u,
                     ab + (size_t)r * N_ + kt * 16 + c * 4);
            }
        }
        // B: 16 k-rows x 128 cols = 512 chunks
        #pragma unroll
        for (int it = 0; it < 2; ++it) {
            int q = tid + it * 256;
            int r = q >> 5, c4 = (q & 31) * 4;
            int m = kt * 16 + r;
            int p = p0 + (c4 >> 6), hd = c4 & 63;
            CP16(sb + (uint32_t)(r * AP_BROW + c4) * 4u,
                 vb + (size_t)m * P_ * C_ + (size_t)p * C_ + hd);
        }
    };

    load_stage(0, 0); CP_COMMIT();
    load_stage(1, 1); CP_COMMIT();

    int lrow = lane & 7;
    int lb3 = (lane >> 3) & 1;
    int lb4 = lane >> 4;
    int bk = lane & 3, bn = lane >> 2;

    #pragma unroll 1
    for (int kt = 0; kt < 6; ++kt) {
        CP_WAIT1();
        __syncthreads();
        if (kt + 2 < 6) load_stage((kt + 2) % 3, kt + 2);
        CP_COMMIT();

        uint32_t sa = smem_base + (kt % 3) * AP_STAGE;
        const float* bsp = smem + ((kt % 3) * AP_STAGE + AP_TILEA) / 4;

        #pragma unroll
        for (int ks = 0; ks < 2; ++ks) {
            uint32_t a[3][4];
            #pragma unroll
            for (int mi = 0; mi < 3; ++mi) {
                int r = wm * 48 + mi * 16 + lb3 * 8 + lrow;
                int ch = ks * 2 + lb4;
                LDSM4(a[mi][0], a[mi][1], a[mi][2], a[mi][3],
                      sa + (uint32_t)(r * AP_AROW + ch * 4) * 4u);
            }
            uint32_t b0[4], b1[4];
            #pragma unroll
            for (int ni = 0; ni < 4; ++ni) {
                int n0 = wn * 32 + ni * 8 + bn;
                int k0 = ks * 8 + bk;
                b0[ni] = __float_as_uint(bsp[k0 * AP_BROW + n0]);
                b1[ni] = __float_as_uint(bsp[(k0 + 4) * AP_BROW + n0]);
            }
            #pragma unroll
            for (int mi = 0; mi < 3; ++mi)
                #pragma unroll
                for (int ni = 0; ni < 4; ++ni)
                    MMA_TF32(acc[mi][ni][0], acc[mi][ni][1], acc[mi][ni][2], acc[mi][ni][3],
                             a[mi][0], a[mi][1], a[mi][2], a[mi][3], b0[ni], b1[ni]);
        }
    }

    int er = lane >> 2;
    int ec = (lane & 3) * 2;
    #pragma unroll
    for (int ni = 0; ni < 4; ++ni) {
        int col = wn * 32 + ni * 8 + ec;            // 0..127 within tile
        int p = p0 + (col >> 6), hd = col & 63;
        #pragma unroll
        for (int mi = 0; mi < 3; ++mi) {
            int n = wm * 48 + mi * 16 + er;
            float* op = out + (((size_t)(b * N_ + n) * P_) + p) * C_ + h * HD_ + hd;
            *(float2*)op = make_float2(f2tff(acc[mi][ni][0]), f2tff(acc[mi][ni][1]));
            float* op2 = out + (((size_t)(b * N_ + n + 8) * P_) + p) * C_ + h * HD_ + hd;
            *(float2*)op2 = make_float2(f2tff(acc[mi][ni][2]), f2tff(acc[mi][ni][3]));
        }
    }
}

// ---------------------------------------------------------------------------
// Weight transpose + tf32 rounding
// ---------------------------------------------------------------------------
__global__ void wtrans_kernel(const float* __restrict__ W, float* __restrict__ Wt, int ldw) {
    __shared__ float t[32][33];
    int n0 = blockIdx.x * 32, k0 = blockIdx.y * 32;
    int tx = threadIdx.x, ty = threadIdx.y;
    #pragma unroll
    for (int i = 0; i < 32; i += 8)
        t[ty + i][tx] = W[(size_t)(k0 + ty + i) * ldw + n0 + tx];
    __syncthreads();
    #pragma unroll
    for (int i = 0; i < 32; i += 8)
        Wt[(size_t)(n0 + ty + i) * C_ + k0 + tx] = f2tff(t[tx][ty + i]);
}

__global__ void cvt_kernel(const float* __restrict__ in, float* __restrict__ out) {
    size_t i = ((size_t)blockIdx.x * 256 + threadIdx.x) * 4;
    float4 v = *(const float4*)(in + i);
    *(float4*)(out + i) = make_float4(f2tff(v.x), f2tff(v.y), f2tff(v.z), f2tff(v.w));
}

__global__ void pool_kernel(const float* __restrict__ x, float* __restrict__ xbar) {
    int bn = blockIdx.x;
    const float* xp = x + (size_t)bn * P_ * C_;
    for (int c = threadIdx.x; c < C_; c += 256) {
        float s = 0.f;
        #pragma unroll 8
        for (int p = 0; p < P_; ++p) s += xp[(size_t)p * C_ + c];
        xbar[(size_t)bn * C_ + c] = f2tff(s * (1.0f / 64.0f));
    }
}

__global__ void attn_kernel(const float* __restrict__ qk, float* __restrict__ attn) {
    __shared__ float qs[N_][HD_];
    __shared__ float ks[N_][HD_];
    int b = blockIdx.x >> 4, h = blockIdx.x & 15;
    for (int i = threadIdx.x; i < N_ * HD_; i += 128) {
        int n = i >> 6, d = i & 63;
        const float* base = qk + ((size_t)(b * N_ + n)) * (2 * C_) + h * HD_ + d;
        qs[n][d] = base[0];
        ks[n][d] = base[C_];
    }
    __syncthreads();
    int n = threadIdx.x;
    if (n < N_) {
        float* row = attn + ((size_t)blockIdx.x * N_ + n) * N_;
        float mx = -1e30f;
        for (int m = 0; m < N_; ++m) {
            float dot = 0.f;
            #pragma unroll
            for (int d = 0; d < HD_; ++d) dot += qs[n][d] * ks[m][d];
            dot *= 0.125f;
            row[m] = dot;
            mx = fmaxf(mx, dot);
        }
        float sum = 0.f;
        float tmp[N_];
        for (int m = 0; m < N_; ++m) { float e = __expf(row[m] - mx); tmp[m] = e; sum += e; }
        float inv = 1.f / sum;
        for (int m = 0; m < N_; ++m) row[m] = f2tff(tmp[m] * inv);
    }
}

// ---------------------------------------------------------------------------
extern "C" void kernel_launch(void* const* d_in, const int* in_sizes, int n_in,
                              void* d_out, int out_size)
{
    const float* x     = (const float*)d_in[0];
    const float* Wqkv  = (const float*)d_in[1];
    const float* Wproj = (const float*)d_in[2];
    const float* bproj = (const float*)d_in[3];
    float* out = (float*)d_out;

    float *xbar, *qkbuf, *attnbuf, *vbuf, *obuf, *xt, *wqkt, *wvt, *wpt;
    cudaGetSymbolAddress((void**)&xbar,    g_xbar);
    cudaGetSymbolAddress((void**)&qkbuf,   g_qk);
    cudaGetSymbolAddress((void**)&attnbuf, g_attn);
    cudaGetSymbolAddress((void**)&vbuf,    g_v);
    cudaGetSymbolAddress((void**)&obuf,    g_o);
    cudaGetSymbolAddress((void**)&xt,      g_xt);
    cudaGetSymbolAddress((void**)&wqkt,    g_wqkt);
    cudaGetSymbolAddress((void**)&wvt,     g_wvt);
    cudaGetSymbolAddress((void**)&wpt,     g_wpt);

    cudaFuncSetAttribute(tc_gemm, cudaFuncAttributeMaxDynamicSharedMemorySize, TC_SMEM);
    cudaFuncSetAttribute(apply_tc, cudaFuncAttributeMaxDynamicSharedMemorySize, AP_SMEM);

    // 0) weight transposes (+tf32) and activation rounding
    wtrans_kernel<<<dim3(64, 32), dim3(32, 8)>>>(Wqkv, wqkt, 3 * C_);
    wtrans_kernel<<<dim3(32, 32), dim3(32, 8)>>>(Wqkv + 2 * C_, wvt, 3 * C_);
    wtrans_kernel<<<dim3(32, 32), dim3(32, 8)>>>(Wproj, wpt, C_);
    cvt_kernel<<<M_ROWS, 256>>>(x, xt);
    // 1) pool (tf32-rounded)
    pool_kernel<<<B_ * N_, 256>>>(x, xbar);
    // 2) q,k = xbar @ W_qk
    tc_gemm<<<dim3(8, 3), 256, TC_SMEM>>>(xbar, wqkt, qkbuf, nullptr, 1024, C_, C_, 2 * C_, 0);
    // 3) scores + softmax (tf32-rounded probs)
    attn_kernel<<<B_ * H_, 128>>>(qkbuf, attnbuf);
    // 4) v = x @ W_v (tf32-rounded output for apply_tc)
    tc_gemm<<<dim3(4, 192), 256, TC_SMEM>>>(xt, wvt, vbuf, nullptr, 1024, C_, C_, C_, 1);
    // 5) attention apply on tensor cores (tf32-rounded output)
    apply_tc<<<dim3(32, 64), 256, AP_SMEM>>>(vbuf, attnbuf, obuf);
    // 6) y = o @ W_proj + b
    tc_gemm<<<dim3(4, 192), 256, TC_SMEM>>>(obuf, wpt, out, bproj, 1024, C_, C_, C_, 0);
}

// round 8
// speedup vs baseline: 3.3224x; 1.1859x over previous
#include <cuda_runtime.h>
#include <math.h>
#include <stdint.h>

// Problem constants
#define B_ 4
#define N_ 96
#define P_ 64
#define C_ 1024
#define H_ 16
#define HD_ 64
#define M_ROWS (B_*N_*P_)   // 24576

// Scratch (device globals: allocation-free contract)
__device__ float g_xbar[B_*N_*C_];        // pooled input, tf32-rounded
__device__ float g_qk[B_*N_*2*C_];        // q|k projections
__device__ float g_attn[B_*H_*N_*N_];     // softmax weights (tf32-rounded)
__device__ float g_v[M_ROWS*C_];          // x @ W_v (tf32-rounded)
__device__ float g_o[M_ROWS*C_];          // attn-applied (tf32-rounded)
__device__ float g_xt[M_ROWS*C_];         // x, tf32-rounded
__device__ float g_wqkt[2*C_*C_];         // W_qk^T [n][k], tf32-rounded
__device__ float g_wvt[C_*C_];            // W_v^T
__device__ float g_wpt[C_*C_];            // W_proj^T

__device__ __forceinline__ float f2tff(float f) {
    uint32_t r; asm("cvt.rna.tf32.f32 %0, %1;" : "=r"(r) : "f"(f));
    return __uint_as_float(r);
}

#define LDSM4(R0,R1,R2,R3,ADDR) \
    asm volatile("ldmatrix.sync.aligned.m8n8.x4.shared.b16 {%0,%1,%2,%3}, [%4];" \
        : "=r"(R0),"=r"(R1),"=r"(R2),"=r"(R3) : "r"(ADDR))

#define MMA_TF32(C0,C1,C2,C3,A0,A1,A2,A3,B0,B1) \
    asm volatile("mma.sync.aligned.m16n8k8.row.col.f32.tf32.tf32.f32 " \
        "{%0,%1,%2,%3}, {%4,%5,%6,%7}, {%8,%9}, {%0,%1,%2,%3};" \
        : "+f"(C0),"+f"(C1),"+f"(C2),"+f"(C3) \
        : "r"(A0),"r"(A1),"r"(A2),"r"(A3),"r"(B0),"r"(B1))

#define CP16(DST, SRC) \
    asm volatile("cp.async.cg.shared.global [%0], [%1], 16;" :: "r"(DST), "l"(SRC) : "memory")
#define CP_COMMIT() asm volatile("cp.async.commit_group;" ::: "memory")
#define CP_WAIT1()  asm volatile("cp.async.wait_group 1;" ::: "memory")

// ---------------------------------------------------------------------------
// TF32 tensor GEMM v5: C = A[M,K] @ Bt[N,K]^T (+bias, opt tf32-round output)
// CTA tile 128x64, 128 threads (4 warps: 2M x 2N), warp tile 64x32, KTILE=16,
// 3-stage cp.async, stride-20 smem rows, fragments via ldmatrix.
// Small CTA footprint (45 KB smem, <=128 regs) -> 4 CTAs/SM for latency hiding.
// ---------------------------------------------------------------------------
#define SROW 20
#define TILEA_B (128 * SROW * 4)            // 10240
#define TILEB_B (64 * SROW * 4)             // 5120
#define STAGEB  (TILEA_B + TILEB_B)         // 15360
#define NSTAGE 3
#define TC_SMEM (NSTAGE * STAGEB)           // 46080

__global__ void __launch_bounds__(128, 4) tc_gemm(
    const float* __restrict__ A, const float* __restrict__ Bt,
    float* __restrict__ Cm, const float* __restrict__ bias,
    int K, int lda, int ldb, int ldc, int roundOut)
{
    extern __shared__ float smem[];
    uint32_t smem_base = (uint32_t)__cvta_generic_to_shared(smem);
    int tid = threadIdx.x;
    int lane = tid & 31, warp = tid >> 5;
    int wm = warp & 1, wn = warp >> 1;

    const float* Ab = A + (size_t)blockIdx.y * 128 * lda;
    const float* Bb = Bt + (size_t)blockIdx.x * 64 * ldb;

    float acc[4][4][4];
    #pragma unroll
    for (int i = 0; i < 4; ++i)
        #pragma unroll
        for (int j = 0; j < 4; ++j)
            #pragma unroll
            for (int r = 0; r < 4; ++r) acc[i][j][r] = 0.f;

    auto load_stage = [&](int s, int kt) {
        uint32_t sa = smem_base + s * STAGEB;
        uint32_t sb = sa + TILEA_B;
        #pragma unroll
        for (int it = 0; it < 4; ++it) {          // A: 512 chunks
            int q = tid + it * 128;
            int r = q >> 2, c = q & 3;
            CP16(sa + (uint32_t)(r * SROW + c * 4) * 4u,
                 Ab + (size_t)r * lda + kt * 16 + c * 4);
        }
        #pragma unroll
        for (int it = 0; it < 2; ++it) {          // B: 256 chunks
            int q = tid + it * 128;
            int r = q >> 2, c = q & 3;
            CP16(sb + (uint32_t)(r * SROW + c * 4) * 4u,
                 Bb + (size_t)r * ldb + kt * 16 + c * 4);
        }
    };

    int nt = K / 16;
    load_stage(0, 0); CP_COMMIT();
    load_stage(1, 1); CP_COMMIT();

    int lrow = lane & 7;
    int lb3 = (lane >> 3) & 1;
    int lb4 = lane >> 4;

    #pragma unroll 1
    for (int kt = 0; kt < nt; ++kt) {
        CP_WAIT1();
        __syncthreads();
        if (kt + 2 < nt) load_stage((kt + 2) % NSTAGE, kt + 2);
        CP_COMMIT();

        uint32_t sa = smem_base + (kt % NSTAGE) * STAGEB;
        uint32_t sb = sa + TILEA_B;

        #pragma unroll
        for (int ks = 0; ks < 2; ++ks) {
            uint32_t a[4][4], b[2][4];
            #pragma unroll
            for (int mi = 0; mi < 4; ++mi) {
                int r = wm * 64 + mi * 16 + lb3 * 8 + lrow;
                int ch = ks * 2 + lb4;
                LDSM4(a[mi][0], a[mi][1], a[mi][2], a[mi][3],
                      sa + (uint32_t)(r * SROW + ch * 4) * 4u);
            }
            #pragma unroll
            for (int pi = 0; pi < 2; ++pi) {
                int r = wn * 32 + pi * 16 + lb4 * 8 + lrow;
                int ch = ks * 2 + lb3;
                LDSM4(b[pi][0], b[pi][1], b[pi][2], b[pi][3],
                      sb + (uint32_t)(r * SROW + ch * 4) * 4u);
            }
            #pragma unroll
            for (int mi = 0; mi < 4; ++mi)
                #pragma unroll
                for (int ni = 0; ni < 4; ++ni)
                    MMA_TF32(acc[mi][ni][0], acc[mi][ni][1], acc[mi][ni][2], acc[mi][ni][3],
                             a[mi][0], a[mi][1], a[mi][2], a[mi][3],
                             b[ni >> 1][(ni & 1) * 2], b[ni >> 1][(ni & 1) * 2 + 1]);
        }
    }

    int cm = blockIdx.y * 128 + wm * 64;
    int cn = blockIdx.x * 64 + wn * 32;
    int er = lane >> 2;
    int ec = (lane & 3) * 2;
    #pragma unroll
    for (int ni = 0; ni < 4; ++ni) {
        int col = cn + ni * 8 + ec;
        float bb0 = bias ? bias[col] : 0.f;
        float bb1 = bias ? bias[col + 1] : 0.f;
        #pragma unroll
        for (int mi = 0; mi < 4; ++mi) {
            int row = cm + mi * 16 + er;
            float v0 = acc[mi][ni][0] + bb0, v1 = acc[mi][ni][1] + bb1;
            float v2 = acc[mi][ni][2] + bb0, v3 = acc[mi][ni][3] + bb1;
            if (roundOut) { v0 = f2tff(v0); v1 = f2tff(v1); v2 = f2tff(v2); v3 = f2tff(v3); }
            *(float2*)(Cm + (size_t)row * ldc + col) = make_float2(v0, v1);
            *(float2*)(Cm + (size_t)(row + 8) * ldc + col) = make_float2(v2, v3);
        }
    }
}

// ---------------------------------------------------------------------------
// apply_tc: per (b,h) GEMM  o[n, (p,hd)] = attn[n,m] @ v[m, (p,hd)]
// CTA tile 96x128 (2 p-values x 64 hd), warp tile 48x32, K=96 (6 k-tiles).
// ---------------------------------------------------------------------------
#define AP_AROW 20
#define AP_BROW 136
#define AP_TILEA (96 * AP_AROW * 4)     // 7680
#define AP_TILEB (16 * AP_BROW * 4)     // 8704
#define AP_STAGE (AP_TILEA + AP_TILEB)  // 16384
#define AP_SMEM  (3 * AP_STAGE)         // 49152

__global__ void __launch_bounds__(256) apply_tc(
    const float* __restrict__ v, const float* __restrict__ attn, float* __restrict__ out)
{
    extern __shared__ float smem[];
    uint32_t smem_base = (uint32_t)__cvta_generic_to_shared(smem);
    int tid = threadIdx.x;
    int lane = tid & 31, warp = tid >> 5;
    int wm = warp & 1, wn = warp >> 1;

    int bh = blockIdx.y;
    int b = bh >> 4, h = bh & 15;
    int p0 = blockIdx.x * 2;

    const float* ab = attn + (size_t)bh * N_ * N_;
    const float* vb = v + (size_t)b * N_ * P_ * C_ + h * HD_;

    float acc[3][4][4];
    #pragma unroll
    for (int i = 0; i < 3; ++i)
        #pragma unroll
        for (int j = 0; j < 4; ++j)
            #pragma unroll
            for (int r = 0; r < 4; ++r) acc[i][j][r] = 0.f;

    auto load_stage = [&](int s, int kt) {
        uint32_t sa = smem_base + s * AP_STAGE;
        uint32_t sb = sa + AP_TILEA;
        {
            int q = tid;
            int r = q >> 2, c = q & 3;
            CP16(sa + (uint32_t)(r * AP_AROW + c * 4) * 4u,
                 ab + (size_t)r * N_ + kt * 16 + c * 4);
            if (tid < 128) {
                q = tid + 256; r = q >> 2; c = q & 3;
                CP16(sa + (uint32_t)(r * AP_AROW + c * 4) * 4u,
                     ab + (size_t)r * N_ + kt * 16 + c * 4);
            }
        }
        #pragma unroll
        for (int it = 0; it < 2; ++it) {
            int q = tid + it * 256;
            int r = q >> 5, c4 = (q & 31) * 4;
            int m = kt * 16 + r;
            int p = p0 + (c4 >> 6), hd = c4 & 63;
            CP16(sb + (uint32_t)(r * AP_BROW + c4) * 4u,
                 vb + (size_t)m * P_ * C_ + (size_t)p * C_ + hd);
        }
    };

    load_stage(0, 0); CP_COMMIT();
    load_stage(1, 1); CP_COMMIT();

    int lrow = lane & 7;
    int lb3 = (lane >> 3) & 1;
    int lb4 = lane >> 4;
    int bk = lane & 3, bn = lane >> 2;

    #pragma unroll 1
    for (int kt = 0; kt < 6; ++kt) {
        CP_WAIT1();
        __syncthreads();
        if (kt + 2 < 6) load_stage((kt + 2) % 3, kt + 2);
        CP_COMMIT();

        uint32_t sa = smem_base + (kt % 3) * AP_STAGE;
        const float* bsp = smem + ((kt % 3) * AP_STAGE + AP_TILEA) / 4;

        #pragma unroll
        for (int ks = 0; ks < 2; ++ks) {
            uint32_t a[3][4];
            #pragma unroll
            for (int mi = 0; mi < 3; ++mi) {
                int r = wm * 48 + mi * 16 + lb3 * 8 + lrow;
                int ch = ks * 2 + lb4;
                LDSM4(a[mi][0], a[mi][1], a[mi][2], a[mi][3],
                      sa + (uint32_t)(r * AP_AROW + ch * 4) * 4u);
            }
            uint32_t b0[4], b1[4];
            #pragma unroll
            for (int ni = 0; ni < 4; ++ni) {
                int n0 = wn * 32 + ni * 8 + bn;
                int k0 = ks * 8 + bk;
                b0[ni] = __float_as_uint(bsp[k0 * AP_BROW + n0]);
                b1[ni] = __float_as_uint(bsp[(k0 + 4) * AP_BROW + n0]);
            }
            #pragma unroll
            for (int mi = 0; mi < 3; ++mi)
                #pragma unroll
                for (int ni = 0; ni < 4; ++ni)
                    MMA_TF32(acc[mi][ni][0], acc[mi][ni][1], acc[mi][ni][2], acc[mi][ni][3],
                             a[mi][0], a[mi][1], a[mi][2], a[mi][3], b0[ni], b1[ni]);
        }
    }

    int er = lane >> 2;
    int ec = (lane & 3) * 2;
    #pragma unroll
    for (int ni = 0; ni < 4; ++ni) {
        int col = wn * 32 + ni * 8 + ec;
        int p = p0 + (col >> 6), hd = col & 63;
        #pragma unroll
        for (int mi = 0; mi < 3; ++mi) {
            int n = wm * 48 + mi * 16 + er;
            float* op = out + (((size_t)(b * N_ + n) * P_) + p) * C_ + h * HD_ + hd;
            *(float2*)op = make_float2(f2tff(acc[mi][ni][0]), f2tff(acc[mi][ni][1]));
            float* op2 = out + (((size_t)(b * N_ + n + 8) * P_) + p) * C_ + h * HD_ + hd;
            *(float2*)op2 = make_float2(f2tff(acc[mi][ni][2]), f2tff(acc[mi][ni][3]));
        }
    }
}

// ---------------------------------------------------------------------------
// Weight transpose + tf32 rounding
// ---------------------------------------------------------------------------
__global__ void wtrans_kernel(const float* __restrict__ W, float* __restrict__ Wt, int ldw) {
    __shared__ float t[32][33];
    int n0 = blockIdx.x * 32, k0 = blockIdx.y * 32;
    int tx = threadIdx.x, ty = threadIdx.y;
    #pragma unroll
    for (int i = 0; i < 32; i += 8)
        t[ty + i][tx] = W[(size_t)(k0 + ty + i) * ldw + n0 + tx];
    __syncthreads();
    #pragma unroll
    for (int i = 0; i < 32; i += 8)
        Wt[(size_t)(n0 + ty + i) * C_ + k0 + tx] = f2tff(t[tx][ty + i]);
}

__global__ void cvt_kernel(const float* __restrict__ in, float* __restrict__ out) {
    size_t i = ((size_t)blockIdx.x * 256 + threadIdx.x) * 4;
    float4 v = *(const float4*)(in + i);
    *(float4*)(out + i) = make_float4(f2tff(v.x), f2tff(v.y), f2tff(v.z), f2tff(v.w));
}

__global__ void pool_kernel(const float* __restrict__ x, float* __restrict__ xbar) {
    int bn = blockIdx.x;
    const float* xp = x + (size_t)bn * P_ * C_;
    for (int c = threadIdx.x; c < C_; c += 256) {
        float s = 0.f;
        #pragma unroll 8
        for (int p = 0; p < P_; ++p) s += xp[(size_t)p * C_ + c];
        xbar[(size_t)bn * C_ + c] = f2tff(s * (1.0f / 64.0f));
    }
}

__global__ void attn_kernel(const float* __restrict__ qk, float* __restrict__ attn) {
    __shared__ float qs[N_][HD_];
    __shared__ float ks[N_][HD_];
    int b = blockIdx.x >> 4, h = blockIdx.x & 15;
    for (int i = threadIdx.x; i < N_ * HD_; i += 128) {
        int n = i >> 6, d = i & 63;
        const float* base = qk + ((size_t)(b * N_ + n)) * (2 * C_) + h * HD_ + d;
        qs[n][d] = base[0];
        ks[n][d] = base[C_];
    }
    __syncthreads();
    int n = threadIdx.x;
    if (n < N_) {
        float* row = attn + ((size_t)blockIdx.x * N_ + n) * N_;
        float mx = -1e30f;
        for (int m = 0; m < N_; ++m) {
            float dot = 0.f;
            #pragma unroll
            for (int d = 0; d < HD_; ++d) dot += qs[n][d] * ks[m][d];
            dot *= 0.125f;
            row[m] = dot;
            mx = fmaxf(mx, dot);
        }
        float sum = 0.f;
        float tmp[N_];
        for (int m = 0; m < N_; ++m) { float e = __expf(row[m] - mx); tmp[m] = e; sum += e; }
        float inv = 1.f / sum;
        for (int m = 0; m < N_; ++m) row[m] = f2tff(tmp[m] * inv);
    }
}

// ---------------------------------------------------------------------------
extern "C" void kernel_launch(void* const* d_in, const int* in_sizes, int n_in,
                              void* d_out, int out_size)
{
    const float* x     = (const float*)d_in[0];
    const float* Wqkv  = (const float*)d_in[1];
    const float* Wproj = (const float*)d_in[2];
    const float* bproj = (const float*)d_in[3];
    float* out = (float*)d_out;

    float *xbar, *qkbuf, *attnbuf, *vbuf, *obuf, *xt, *wqkt, *wvt, *wpt;
    cudaGetSymbolAddress((void**)&xbar,    g_xbar);
    cudaGetSymbolAddress((void**)&qkbuf,   g_qk);
    cudaGetSymbolAddress((void**)&attnbuf, g_attn);
    cudaGetSymbolAddress((void**)&vbuf,    g_v);
    cudaGetSymbolAddress((void**)&obuf,    g_o);
    cudaGetSymbolAddress((void**)&xt,      g_xt);
    cudaGetSymbolAddress((void**)&wqkt,    g_wqkt);
    cudaGetSymbolAddress((void**)&wvt,     g_wvt);
    cudaGetSymbolAddress((void**)&wpt,     g_wpt);

    cudaFuncSetAttribute(tc_gemm, cudaFuncAttributeMaxDynamicSharedMemorySize, TC_SMEM);
    cudaFuncSetAttribute(apply_tc, cudaFuncAttributeMaxDynamicSharedMemorySize, AP_SMEM);

    // 0) weight transposes (+tf32) and activation rounding
    wtrans_kernel<<<dim3(64, 32), dim3(32, 8)>>>(Wqkv, wqkt, 3 * C_);
    wtrans_kernel<<<dim3(32, 32), dim3(32, 8)>>>(Wqkv + 2 * C_, wvt, 3 * C_);
    wtrans_kernel<<<dim3(32, 32), dim3(32, 8)>>>(Wproj, wpt, C_);
    cvt_kernel<<<M_ROWS, 256>>>(x, xt);
    // 1) pool (tf32-rounded)
    pool_kernel<<<B_ * N_, 256>>>(x, xbar);
    // 2) q,k = xbar @ W_qk
    tc_gemm<<<dim3(32, 3), 128, TC_SMEM>>>(xbar, wqkt, qkbuf, nullptr, 1024, C_, C_, 2 * C_, 0);
    // 3) scores + softmax (tf32-rounded probs)
    attn_kernel<<<B_ * H_, 128>>>(qkbuf, attnbuf);
    // 4) v = x @ W_v (tf32-rounded output for apply_tc)
    tc_gemm<<<dim3(16, 192), 128, TC_SMEM>>>(xt, wvt, vbuf, nullptr, 1024, C_, C_, C_, 1);
    // 5) attention apply on tensor cores (tf32-rounded output)
    apply_tc<<<dim3(32, 64), 256, AP_SMEM>>>(vbuf, attnbuf, obuf);
    // 6) y = o @ W_proj + b
    tc_gemm<<<dim3(16, 192), 128, TC_SMEM>>>(obuf, wpt, out, bproj, 1024, C_, C_, C_, 0);
}

// round 9
// speedup vs baseline: 3.5781x; 1.0770x over previous
#include <cuda_runtime.h>
#include <math.h>
#include <stdint.h>

// Problem constants
#define B_ 4
#define N_ 96
#define P_ 64
#define C_ 1024
#define H_ 16
#define HD_ 64
#define M_ROWS (B_*N_*P_)   // 24576

// Scratch (device globals: allocation-free contract)
__device__ float g_xbar[B_*N_*C_];        // pooled input, tf32-rounded
__device__ float g_qk[B_*N_*2*C_];        // q|k projections
__device__ float g_attn[B_*H_*N_*N_];     // softmax weights (tf32-rounded)
__device__ float g_v[M_ROWS*C_];          // x @ W_v (tf32-rounded)
__device__ float g_o[M_ROWS*C_];          // attn-applied (tf32-rounded)
__device__ float g_wqkt[2*C_*C_];         // W_qk^T [n][k], tf32-rounded
__device__ float g_wvt[C_*C_];            // W_v^T
__device__ float g_wpt[C_*C_];            // W_proj^T

__device__ __forceinline__ float f2tff(float f) {
    uint32_t r; asm("cvt.rna.tf32.f32 %0, %1;" : "=r"(r) : "f"(f));
    return __uint_as_float(r);
}

#define LDSM4(R0,R1,R2,R3,ADDR) \
    asm volatile("ldmatrix.sync.aligned.m8n8.x4.shared.b16 {%0,%1,%2,%3}, [%4];" \
        : "=r"(R0),"=r"(R1),"=r"(R2),"=r"(R3) : "r"(ADDR))

#define MMA_TF32(C0,C1,C2,C3,A0,A1,A2,A3,B0,B1) \
    asm volatile("mma.sync.aligned.m16n8k8.row.col.f32.tf32.tf32.f32 " \
        "{%0,%1,%2,%3}, {%4,%5,%6,%7}, {%8,%9}, {%0,%1,%2,%3};" \
        : "+f"(C0),"+f"(C1),"+f"(C2),"+f"(C3) \
        : "r"(A0),"r"(A1),"r"(A2),"r"(A3),"r"(B0),"r"(B1))

#define CP16(DST, SRC) \
    asm volatile("cp.async.cg.shared.global [%0], [%1], 16;" :: "r"(DST), "l"(SRC) : "memory")
#define CP_COMMIT() asm volatile("cp.async.commit_group;" ::: "memory")
#define CP_WAIT1()  asm volatile("cp.async.wait_group 1;" ::: "memory")

// ---------------------------------------------------------------------------
// TF32 tensor GEMM: C = A[M,K] @ Bt[N,K]^T (+bias, opt tf32-round output)
// CTA tile 128x64, 128 threads (4 warps: 2M x 2N), warp tile 64x32, KTILE=16,
// 3-stage cp.async, stride-20 smem rows, fragments via ldmatrix.
// 45 KB smem, <=128 regs -> 4 CTAs/SM. A may be raw fp32 (HW tf32-truncates).
// ---------------------------------------------------------------------------
#define SROW 20
#define TILEA_B (128 * SROW * 4)            // 10240
#define TILEB_B (64 * SROW * 4)             // 5120
#define STAGEB  (TILEA_B + TILEB_B)         // 15360
#define NSTAGE 3
#define TC_SMEM (NSTAGE * STAGEB)           // 46080

__global__ void __launch_bounds__(128, 4) tc_gemm(
    const float* __restrict__ A, const float* __restrict__ Bt,
    float* __restrict__ Cm, const float* __restrict__ bias,
    int K, int lda, int ldb, int ldc, int roundOut)
{
    extern __shared__ float smem[];
    uint32_t smem_base = (uint32_t)__cvta_generic_to_shared(smem);
    int tid = threadIdx.x;
    int lane = tid & 31, warp = tid >> 5;
    int wm = warp & 1, wn = warp >> 1;

    const float* Ab = A + (size_t)blockIdx.y * 128 * lda;
    const float* Bb = Bt + (size_t)blockIdx.x * 64 * ldb;

    float acc[4][4][4];
    #pragma unroll
    for (int i = 0; i < 4; ++i)
        #pragma unroll
        for (int j = 0; j < 4; ++j)
            #pragma unroll
            for (int r = 0; r < 4; ++r) acc[i][j][r] = 0.f;

    auto load_stage = [&](int s, int kt) {
        uint32_t sa = smem_base + s * STAGEB;
        uint32_t sb = sa + TILEA_B;
        #pragma unroll
        for (int it = 0; it < 4; ++it) {          // A: 512 chunks
            int q = tid + it * 128;
            int r = q >> 2, c = q & 3;
            CP16(sa + (uint32_t)(r * SROW + c * 4) * 4u,
                 Ab + (size_t)r * lda + kt * 16 + c * 4);
        }
        #pragma unroll
        for (int it = 0; it < 2; ++it) {          // B: 256 chunks
            int q = tid + it * 128;
            int r = q >> 2, c = q & 3;
            CP16(sb + (uint32_t)(r * SROW + c * 4) * 4u,
                 Bb + (size_t)r * ldb + kt * 16 + c * 4);
        }
    };

    int nt = K / 16;
    load_stage(0, 0); CP_COMMIT();
    load_stage(1, 1); CP_COMMIT();

    int lrow = lane & 7;
    int lb3 = (lane >> 3) & 1;
    int lb4 = lane >> 4;

    #pragma unroll 1
    for (int kt = 0; kt < nt; ++kt) {
        CP_WAIT1();
        __syncthreads();
        if (kt + 2 < nt) load_stage((kt + 2) % NSTAGE, kt + 2);
        CP_COMMIT();

        uint32_t sa = smem_base + (kt % NSTAGE) * STAGEB;
        uint32_t sb = sa + TILEA_B;

        #pragma unroll
        for (int ks = 0; ks < 2; ++ks) {
            uint32_t a[4][4], b[2][4];
            #pragma unroll
            for (int mi = 0; mi < 4; ++mi) {
                int r = wm * 64 + mi * 16 + lb3 * 8 + lrow;
                int ch = ks * 2 + lb4;
                LDSM4(a[mi][0], a[mi][1], a[mi][2], a[mi][3],
                      sa + (uint32_t)(r * SROW + ch * 4) * 4u);
            }
            #pragma unroll
            for (int pi = 0; pi < 2; ++pi) {
                int r = wn * 32 + pi * 16 + lb4 * 8 + lrow;
                int ch = ks * 2 + lb3;
                LDSM4(b[pi][0], b[pi][1], b[pi][2], b[pi][3],
                      sb + (uint32_t)(r * SROW + ch * 4) * 4u);
            }
            #pragma unroll
            for (int mi = 0; mi < 4; ++mi)
                #pragma unroll
                for (int ni = 0; ni < 4; ++ni)
                    MMA_TF32(acc[mi][ni][0], acc[mi][ni][1], acc[mi][ni][2], acc[mi][ni][3],
                             a[mi][0], a[mi][1], a[mi][2], a[mi][3],
                             b[ni >> 1][(ni & 1) * 2], b[ni >> 1][(ni & 1) * 2 + 1]);
        }
    }

    int cm = blockIdx.y * 128 + wm * 64;
    int cn = blockIdx.x * 64 + wn * 32;
    int er = lane >> 2;
    int ec = (lane & 3) * 2;
    #pragma unroll
    for (int ni = 0; ni < 4; ++ni) {
        int col = cn + ni * 8 + ec;
        float bb0 = bias ? bias[col] : 0.f;
        float bb1 = bias ? bias[col + 1] : 0.f;
        #pragma unroll
        for (int mi = 0; mi < 4; ++mi) {
            int row = cm + mi * 16 + er;
            float v0 = acc[mi][ni][0] + bb0, v1 = acc[mi][ni][1] + bb1;
            float v2 = acc[mi][ni][2] + bb0, v3 = acc[mi][ni][3] + bb1;
            if (roundOut) { v0 = f2tff(v0); v1 = f2tff(v1); v2 = f2tff(v2); v3 = f2tff(v3); }
            *(float2*)(Cm + (size_t)row * ldc + col) = make_float2(v0, v1);
            *(float2*)(Cm + (size_t)(row + 8) * ldc + col) = make_float2(v2, v3);
        }
    }
}

// ---------------------------------------------------------------------------
// apply_tc: per (b,h) GEMM  o[n, (p,hd)] = attn[n,m] @ v[m, (p,hd)]
// CTA tile 96x128 (2 p-values x 64 hd), warp tile 48x32, K=96 (6 k-tiles).
// ---------------------------------------------------------------------------
#define AP_AROW 20
#define AP_BROW 136
#define AP_TILEA (96 * AP_AROW * 4)     // 7680
#define AP_TILEB (16 * AP_BROW * 4)     // 8704
#define AP_STAGE (AP_TILEA + AP_TILEB)  // 16384
#define AP_SMEM  (3 * AP_STAGE)         // 49152

__global__ void __launch_bounds__(256) apply_tc(
    const float* __restrict__ v, const float* __restrict__ attn, float* __restrict__ out)
{
    extern __shared__ float smem[];
    uint32_t smem_base = (uint32_t)__cvta_generic_to_shared(smem);
    int tid = threadIdx.x;
    int lane = tid & 31, warp = tid >> 5;
    int wm = warp & 1, wn = warp >> 1;

    int bh = blockIdx.y;
    int b = bh >> 4, h = bh & 15;
    int p0 = blockIdx.x * 2;

    const float* ab = attn + (size_t)bh * N_ * N_;
    const float* vb = v + (size_t)b * N_ * P_ * C_ + h * HD_;

    float acc[3][4][4];
    #pragma unroll
    for (int i = 0; i < 3; ++i)
        #pragma unroll
        for (int j = 0; j < 4; ++j)
            #pragma unroll
            for (int r = 0; r < 4; ++r) acc[i][j][r] = 0.f;

    auto load_stage = [&](int s, int kt) {
        uint32_t sa = smem_base + s * AP_STAGE;
        uint32_t sb = sa + AP_TILEA;
        {
            int q = tid;
            int r = q >> 2, c = q & 3;
            CP16(sa + (uint32_t)(r * AP_AROW + c * 4) * 4u,
                 ab + (size_t)r * N_ + kt * 16 + c * 4);
            if (tid < 128) {
                q = tid + 256; r = q >> 2; c = q & 3;
                CP16(sa + (uint32_t)(r * AP_AROW + c * 4) * 4u,
                     ab + (size_t)r * N_ + kt * 16 + c * 4);
            }
        }
        #pragma unroll
        for (int it = 0; it < 2; ++it) {
            int q = tid + it * 256;
            int r = q >> 5, c4 = (q & 31) * 4;
            int m = kt * 16 + r;
            int p = p0 + (c4 >> 6), hd = c4 & 63;
            CP16(sb + (uint32_t)(r * AP_BROW + c4) * 4u,
                 vb + (size_t)m * P_ * C_ + (size_t)p * C_ + hd);
        }
    };

    load_stage(0, 0); CP_COMMIT();
    load_stage(1, 1); CP_COMMIT();

    int lrow = lane & 7;
    int lb3 = (lane >> 3) & 1;
    int lb4 = lane >> 4;
    int bk = lane & 3, bn = lane >> 2;

    #pragma unroll 1
    for (int kt = 0; kt < 6; ++kt) {
        CP_WAIT1();
        __syncthreads();
        if (kt + 2 < 6) load_stage((kt + 2) % 3, kt + 2);
        CP_COMMIT();

        uint32_t sa = smem_base + (kt % 3) * AP_STAGE;
        const float* bsp = smem + ((kt % 3) * AP_STAGE + AP_TILEA) / 4;

        #pragma unroll
        for (int ks = 0; ks < 2; ++ks) {
            uint32_t a[3][4];
            #pragma unroll
            for (int mi = 0; mi < 3; ++mi) {
                int r = wm * 48 + mi * 16 + lb3 * 8 + lrow;
                int ch = ks * 2 + lb4;
                LDSM4(a[mi][0], a[mi][1], a[mi][2], a[mi][3],
                      sa + (uint32_t)(r * AP_AROW + ch * 4) * 4u);
            }
            uint32_t b0[4], b1[4];
            #pragma unroll
            for (int ni = 0; ni < 4; ++ni) {
                int n0 = wn * 32 + ni * 8 + bn;
                int k0 = ks * 8 + bk;
                b0[ni] = __float_as_uint(bsp[k0 * AP_BROW + n0]);
                b1[ni] = __float_as_uint(bsp[(k0 + 4) * AP_BROW + n0]);
            }
            #pragma unroll
            for (int mi = 0; mi < 3; ++mi)
                #pragma unroll
                for (int ni = 0; ni < 4; ++ni)
                    MMA_TF32(acc[mi][ni][0], acc[mi][ni][1], acc[mi][ni][2], acc[mi][ni][3],
                             a[mi][0], a[mi][1], a[mi][2], a[mi][3], b0[ni], b1[ni]);
        }
    }

    int er = lane >> 2;
    int ec = (lane & 3) * 2;
    #pragma unroll
    for (int ni = 0; ni < 4; ++ni) {
        int col = wn * 32 + ni * 8 + ec;
        int p = p0 + (col >> 6), hd = col & 63;
        #pragma unroll
        for (int mi = 0; mi < 3; ++mi) {
            int n = wm * 48 + mi * 16 + er;
            float* op = out + (((size_t)(b * N_ + n) * P_) + p) * C_ + h * HD_ + hd;
            *(float2*)op = make_float2(f2tff(acc[mi][ni][0]), f2tff(acc[mi][ni][1]));
            float* op2 = out + (((size_t)(b * N_ + n + 8) * P_) + p) * C_ + h * HD_ + hd;
            *(float2*)op2 = make_float2(f2tff(acc[mi][ni][2]), f2tff(acc[mi][ni][3]));
        }
    }
}

// ---------------------------------------------------------------------------
// Weight transpose + tf32 rounding
// ---------------------------------------------------------------------------
__global__ void wtrans_kernel(const float* __restrict__ W, float* __restrict__ Wt, int ldw) {
    __shared__ float t[32][33];
    int n0 = blockIdx.x * 32, k0 = blockIdx.y * 32;
    int tx = threadIdx.x, ty = threadIdx.y;
    #pragma unroll
    for (int i = 0; i < 32; i += 8)
        t[ty + i][tx] = W[(size_t)(k0 + ty + i) * ldw + n0 + tx];
    __syncthreads();
    #pragma unroll
    for (int i = 0; i < 32; i += 8)
        Wt[(size_t)(n0 + ty + i) * C_ + k0 + tx] = f2tff(t[tx][ty + i]);
}

__global__ void pool_kernel(const float* __restrict__ x, float* __restrict__ xbar) {
    int bn = blockIdx.x;
    const float* xp = x + (size_t)bn * P_ * C_;
    for (int c = threadIdx.x; c < C_; c += 256) {
        float s = 0.f;
        #pragma unroll 8
        for (int p = 0; p < P_; ++p) s += xp[(size_t)p * C_ + c];
        xbar[(size_t)bn * C_ + c] = f2tff(s * (1.0f / 64.0f));
    }
}

__global__ void attn_kernel(const float* __restrict__ qk, float* __restrict__ attn) {
    __shared__ float qs[N_][HD_];
    __shared__ float ks[N_][HD_];
    int b = blockIdx.x >> 4, h = blockIdx.x & 15;
    for (int i = threadIdx.x; i < N_ * HD_; i += 128) {
        int n = i >> 6, d = i & 63;
        const float* base = qk + ((size_t)(b * N_ + n)) * (2 * C_) + h * HD_ + d;
        qs[n][d] = base[0];
        ks[n][d] = base[C_];
    }
    __syncthreads();
    int n = threadIdx.x;
    if (n < N_) {
        float* row = attn + ((size_t)blockIdx.x * N_ + n) * N_;
        float mx = -1e30f;
        for (int m = 0; m < N_; ++m) {
            float dot = 0.f;
            #pragma unroll
            for (int d = 0; d < HD_; ++d) dot += qs[n][d] * ks[m][d];
            dot *= 0.125f;
            row[m] = dot;
            mx = fmaxf(mx, dot);
        }
        float sum = 0.f;
        float tmp[N_];
        for (int m = 0; m < N_; ++m) { float e = __expf(row[m] - mx); tmp[m] = e; sum += e; }
        float inv = 1.f / sum;
        for (int m = 0; m < N_; ++m) row[m] = f2tff(tmp[m] * inv);
    }
}

// ---------------------------------------------------------------------------
extern "C" void kernel_launch(void* const* d_in, const int* in_sizes, int n_in,
                              void* d_out, int out_size)
{
    const float* x     = (const float*)d_in[0];
    const float* Wqkv  = (const float*)d_in[1];
    const float* Wproj = (const float*)d_in[2];
    const float* bproj = (const float*)d_in[3];
    float* out = (float*)d_out;

    float *xbar, *qkbuf, *attnbuf, *vbuf, *obuf, *wqkt, *wvt, *wpt;
    cudaGetSymbolAddress((void**)&xbar,    g_xbar);
    cudaGetSymbolAddress((void**)&qkbuf,   g_qk);
    cudaGetSymbolAddress((void**)&attnbuf, g_attn);
    cudaGetSymbolAddress((void**)&vbuf,    g_v);
    cudaGetSymbolAddress((void**)&obuf,    g_o);
    cudaGetSymbolAddress((void**)&wqkt,    g_wqkt);
    cudaGetSymbolAddress((void**)&wvt,     g_wvt);
    cudaGetSymbolAddress((void**)&wpt,     g_wpt);

    cudaFuncSetAttribute(tc_gemm, cudaFuncAttributeMaxDynamicSharedMemorySize, TC_SMEM);
    cudaFuncSetAttribute(apply_tc, cudaFuncAttributeMaxDynamicSharedMemorySize, AP_SMEM);

    // Side streams + fork/join events (created once; host-side only, no device mem)
    static cudaStream_t s2 = nullptr, s3 = nullptr;
    static cudaEvent_t evRoot = nullptr, evAttn = nullptr, evWpt = nullptr;
    if (!s2) {
        cudaStreamCreateWithFlags(&s2, cudaStreamNonBlocking);
        cudaStreamCreateWithFlags(&s3, cudaStreamNonBlocking);
        cudaEventCreateWithFlags(&evRoot, cudaEventDisableTiming);
        cudaEventCreateWithFlags(&evAttn, cudaEventDisableTiming);
        cudaEventCreateWithFlags(&evWpt, cudaEventDisableTiming);
    }

    // Fork from the main (legacy) stream
    cudaEventRecord(evRoot, 0);
    cudaStreamWaitEvent(s2, evRoot, 0);
    cudaStreamWaitEvent(s3, evRoot, 0);

    // s2: qk/attn chain (independent of v-GEMM)
    wtrans_kernel<<<dim3(64, 32), dim3(32, 8), 0, s2>>>(Wqkv, wqkt, 3 * C_);
    pool_kernel<<<B_ * N_, 256, 0, s2>>>(x, xbar);
    tc_gemm<<<dim3(32, 3), 128, TC_SMEM, s2>>>(xbar, wqkt, qkbuf, nullptr, 1024, C_, C_, 2 * C_, 0);
    attn_kernel<<<B_ * H_, 128, 0, s2>>>(qkbuf, attnbuf);
    cudaEventRecord(evAttn, s2);

    // s3: proj-weight transpose
    wtrans_kernel<<<dim3(32, 32), dim3(32, 8), 0, s3>>>(Wproj, wpt, C_);
    cudaEventRecord(evWpt, s3);

    // main stream: v chain (critical path)
    wtrans_kernel<<<dim3(32, 32), dim3(32, 8)>>>(Wqkv + 2 * C_, wvt, 3 * C_);
    tc_gemm<<<dim3(16, 192), 128, TC_SMEM>>>(x, wvt, vbuf, nullptr, 1024, C_, C_, C_, 1);

    // join attn, then apply
    cudaStreamWaitEvent(0, evAttn, 0);
    apply_tc<<<dim3(32, 64), 256, AP_SMEM>>>(vbuf, attnbuf, obuf);

    // join wpt, then proj
    cudaStreamWaitEvent(0, evWpt, 0);
    tc_gemm<<<dim3(16, 192), 128, TC_SMEM>>>(obuf, wpt, out, bproj, 1024, C_, C_, C_, 0);
}

// round 10
// speedup vs baseline: 6.1069x; 1.7067x over previous
#include <cuda_runtime.h>
#include <cuda_fp16.h>
#include <math.h>
#include <stdint.h>

// Problem constants
#define B_ 4
#define N_ 96
#define P_ 64
#define C_ 1024
#define H_ 16
#define HD_ 64
#define M_ROWS (B_*N_*P_)   // 24576

// Scratch (device globals: allocation-free contract)
__device__ __half  g_xh[M_ROWS*C_];       // x, fp16
__device__ __half  g_xbar[B_*N_*C_];      // pooled input, fp16
__device__ float   g_qk[B_*N_*2*C_];      // q|k projections (fp32)
__device__ __half  g_attnh[B_*H_*N_*N_];  // softmax probs, fp16
__device__ __half  g_vh[M_ROWS*C_];       // x @ W_v, fp16
__device__ __half  g_oh[M_ROWS*C_];       // attn-applied, fp16
__device__ __half  g_wqkt[2*C_*C_];       // W_qk^T [n][k], fp16
__device__ __half  g_wvt[C_*C_];          // W_v^T
__device__ __half  g_wpt[C_*C_];          // W_proj^T

#define LDSM4(R0,R1,R2,R3,ADDR) \
    asm volatile("ldmatrix.sync.aligned.m8n8.x4.shared.b16 {%0,%1,%2,%3}, [%4];" \
        : "=r"(R0),"=r"(R1),"=r"(R2),"=r"(R3) : "r"(ADDR))
#define LDSM4T(R0,R1,R2,R3,ADDR) \
    asm volatile("ldmatrix.sync.aligned.m8n8.x4.trans.shared.b16 {%0,%1,%2,%3}, [%4];" \
        : "=r"(R0),"=r"(R1),"=r"(R2),"=r"(R3) : "r"(ADDR))

#define MMA_F16(C0,C1,C2,C3,A0,A1,A2,A3,B0,B1) \
    asm volatile("mma.sync.aligned.m16n8k16.row.col.f32.f16.f16.f32 " \
        "{%0,%1,%2,%3}, {%4,%5,%6,%7}, {%8,%9}, {%0,%1,%2,%3};" \
        : "+f"(C0),"+f"(C1),"+f"(C2),"+f"(C3) \
        : "r"(A0),"r"(A1),"r"(A2),"r"(A3),"r"(B0),"r"(B1))

#define CP16(DST, SRC) \
    asm volatile("cp.async.cg.shared.global [%0], [%1], 16;" :: "r"(DST), "l"(SRC) : "memory")
#define CP_COMMIT() asm volatile("cp.async.commit_group;" ::: "memory")
#define CP_WAIT1()  asm volatile("cp.async.wait_group 1;" ::: "memory")

// ---------------------------------------------------------------------------
// FP16 tensor GEMM: C = A[M,K] @ Bt[N,K]^T (+bias), fp32 accum.
// CTA tile 128x64, 128 threads (4 warps 2M x 2N), warp tile 64x32, KTILE=32,
// 3-stage cp.async. Rows stride 40 halves (80B) -> conflict-free ldmatrix.
// Output fp32 (optionally +bias) or fp16.
// ---------------------------------------------------------------------------
#define SROW16 40                          // halves per row
#define TA16 (128 * SROW16 * 2)            // 10240 B
#define TB16 (64 * SROW16 * 2)             // 5120 B
#define ST16 (TA16 + TB16)                 // 15360 B
#define NST 3
#define TC_SMEM (NST * ST16)               // 46080 B

__global__ void __launch_bounds__(128, 4) tc_gemm(
    const __half* __restrict__ A, const __half* __restrict__ Bt,
    void* __restrict__ Cm, const float* __restrict__ bias,
    int K, int lda, int ldb, int ldc, int outHalf)
{
    extern __shared__ char smem[];
    uint32_t smem_base = (uint32_t)__cvta_generic_to_shared(smem);
    int tid = threadIdx.x;
    int lane = tid & 31, warp = tid >> 5;
    int wm = warp & 1, wn = warp >> 1;

    const __half* Ab = A + (size_t)blockIdx.y * 128 * lda;
    const __half* Bb = Bt + (size_t)blockIdx.x * 64 * ldb;

    float acc[4][4][4];
    #pragma unroll
    for (int i = 0; i < 4; ++i)
        #pragma unroll
        for (int j = 0; j < 4; ++j)
            #pragma unroll
            for (int r = 0; r < 4; ++r) acc[i][j][r] = 0.f;

    auto load_stage = [&](int s, int kt) {
        uint32_t sa = smem_base + s * ST16;
        uint32_t sb = sa + TA16;
        #pragma unroll
        for (int it = 0; it < 4; ++it) {          // A: 512 x 16B
            int q = tid + it * 128;
            int r = q >> 2, c = q & 3;
            CP16(sa + (uint32_t)(r * SROW16 + c * 8) * 2u,
                 Ab + (size_t)r * lda + kt * 32 + c * 8);
        }
        #pragma unroll
        for (int it = 0; it < 2; ++it) {          // B: 256 x 16B
            int q = tid + it * 128;
            int r = q >> 2, c = q & 3;
            CP16(sb + (uint32_t)(r * SROW16 + c * 8) * 2u,
                 Bb + (size_t)r * ldb + kt * 32 + c * 8);
        }
    };

    int nt = K / 32;
    load_stage(0, 0); CP_COMMIT();
    load_stage(1, 1); CP_COMMIT();

    int l7 = lane & 7;
    int lg8 = (lane >> 3) & 1;   // lane/8 parity
    int lg16 = lane >> 4;        // lane/16

    #pragma unroll 1
    for (int kt = 0; kt < nt; ++kt) {
        CP_WAIT1();
        __syncthreads();
        if (kt + 2 < nt) load_stage((kt + 2) % NST, kt + 2);
        CP_COMMIT();

        uint32_t sa = smem_base + (kt % NST) * ST16;
        uint32_t sb = sa + TA16;

        #pragma unroll
        for (int ks = 0; ks < 2; ++ks) {
            int k0 = ks * 16;
            uint32_t a[4][4], b[2][4];
            #pragma unroll
            for (int mi = 0; mi < 4; ++mi) {
                // x4: [r0-7|k0-7],[r8-15|k0-7],[r0-7|k8-15],[r8-15|k8-15]
                int row = wm * 64 + mi * 16 + l7 + lg8 * 8;
                int kc = k0 + lg16 * 8;
                LDSM4(a[mi][0], a[mi][1], a[mi][2], a[mi][3],
                      sa + (uint32_t)(row * SROW16 + kc) * 2u);
            }
            #pragma unroll
            for (int pi = 0; pi < 2; ++pi) {
                // x4: [n0-7|k0-7],[n0-7|k8-15],[n8-15|k0-7],[n8-15|k8-15]
                int nrow = wn * 32 + pi * 16 + l7 + lg16 * 8;
                int kc = k0 + lg8 * 8;
                LDSM4(b[pi][0], b[pi][1], b[pi][2], b[pi][3],
                      sb + (uint32_t)(nrow * SROW16 + kc) * 2u);
            }
            #pragma unroll
            for (int mi = 0; mi < 4; ++mi)
                #pragma unroll
                for (int ni = 0; ni < 4; ++ni)
                    MMA_F16(acc[mi][ni][0], acc[mi][ni][1], acc[mi][ni][2], acc[mi][ni][3],
                            a[mi][0], a[mi][1], a[mi][2], a[mi][3],
                            b[ni >> 1][(ni & 1) * 2], b[ni >> 1][(ni & 1) * 2 + 1]);
        }
    }

    int cm = blockIdx.y * 128 + wm * 64;
    int cn = blockIdx.x * 64 + wn * 32;
    int er = lane >> 2;
    int ec = (lane & 3) * 2;
    #pragma unroll
    for (int ni = 0; ni < 4; ++ni) {
        int col = cn + ni * 8 + ec;
        float bb0 = bias ? bias[col] : 0.f;
        float bb1 = bias ? bias[col + 1] : 0.f;
        #pragma unroll
        for (int mi = 0; mi < 4; ++mi) {
            int row = cm + mi * 16 + er;
            float v0 = acc[mi][ni][0] + bb0, v1 = acc[mi][ni][1] + bb1;
            float v2 = acc[mi][ni][2] + bb0, v3 = acc[mi][ni][3] + bb1;
            if (outHalf) {
                __half* Ch = (__half*)Cm;
                *(__half2*)(Ch + (size_t)row * ldc + col) = __floats2half2_rn(v0, v1);
                *(__half2*)(Ch + (size_t)(row + 8) * ldc + col) = __floats2half2_rn(v2, v3);
            } else {
                float* Cf = (float*)Cm;
                *(float2*)(Cf + (size_t)row * ldc + col) = make_float2(v0, v1);
                *(float2*)(Cf + (size_t)(row + 8) * ldc + col) = make_float2(v2, v3);
            }
        }
    }
}

// ---------------------------------------------------------------------------
// apply_tc: per (b,h) GEMM  o[n, (p,hd)] = attn[n,m] @ v[m, (p,hd)], fp16 in,
// fp16 out, fp32 accum. CTA tile 96x128 (2 p x 64 hd), warp tile 48x32, K=96.
// A [n][k] stride 24 halves (ldmatrix); B [k][n] stride 136 halves
// (ldmatrix.trans). 3-stage cp.async.
// ---------------------------------------------------------------------------
#define AP_AROW 24
#define AP_BROW 136
#define AP_TA (96 * AP_AROW * 2)        // 4608 B
#define AP_TB (16 * AP_BROW * 2)        // 4352 B
#define AP_ST (AP_TA + AP_TB)           // 8960 B
#define AP_SMEM (3 * AP_ST)             // 26880 B

__global__ void __launch_bounds__(256) apply_tc(
    const __half* __restrict__ v, const __half* __restrict__ attn, __half* __restrict__ out)
{
    extern __shared__ char smem[];
    uint32_t smem_base = (uint32_t)__cvta_generic_to_shared(smem);
    int tid = threadIdx.x;
    int lane = tid & 31, warp = tid >> 5;
    int wm = warp & 1, wn = warp >> 1;

    int bh = blockIdx.y;
    int b = bh >> 4, h = bh & 15;
    int p0 = blockIdx.x * 2;

    const __half* ab = attn + (size_t)bh * N_ * N_;
    const __half* vb = v + (size_t)b * N_ * P_ * C_ + h * HD_;

    float acc[3][4][4];
    #pragma unroll
    for (int i = 0; i < 3; ++i)
        #pragma unroll
        for (int j = 0; j < 4; ++j)
            #pragma unroll
            for (int r = 0; r < 4; ++r) acc[i][j][r] = 0.f;

    auto load_stage = [&](int s, int kt) {
        uint32_t sa = smem_base + s * AP_ST;
        uint32_t sb = sa + AP_TA;
        if (tid < 192) {                       // A: 96 rows x 2 chunks
            int r = tid >> 1, c = tid & 1;
            CP16(sa + (uint32_t)(r * AP_AROW + c * 8) * 2u,
                 ab + (size_t)r * N_ + kt * 16 + c * 8);
        }
        {                                      // B: 16 k-rows x 16 chunks
            int r = tid >> 4, c = tid & 15;
            int m = kt * 16 + r;
            int p = p0 + (c >> 3), hd = (c & 7) * 8;
            CP16(sb + (uint32_t)(r * AP_BROW + c * 8) * 2u,
                 vb + (size_t)m * P_ * C_ + (size_t)p * C_ + hd);
        }
    };

    load_stage(0, 0); CP_COMMIT();
    load_stage(1, 1); CP_COMMIT();

    int l7 = lane & 7;
    int lg8 = (lane >> 3) & 1;
    int lg16 = lane >> 4;

    #pragma unroll 1
    for (int kt = 0; kt < 6; ++kt) {
        CP_WAIT1();
        __syncthreads();
        if (kt + 2 < 6) load_stage((kt + 2) % 3, kt + 2);
        CP_COMMIT();

        uint32_t sa = smem_base + (kt % 3) * AP_ST;
        uint32_t sb = sa + AP_TA;

        uint32_t a[3][4], bfr[2][4];
        #pragma unroll
        for (int mi = 0; mi < 3; ++mi) {
            int row = wm * 48 + mi * 16 + l7 + lg8 * 8;
            int kc = lg16 * 8;
            LDSM4(a[mi][0], a[mi][1], a[mi][2], a[mi][3],
                  sa + (uint32_t)(row * AP_AROW + kc) * 2u);
        }
        #pragma unroll
        for (int pi = 0; pi < 2; ++pi) {
            // trans x4: [k0-7|n0-7],[k8-15|n0-7],[k0-7|n8-15],[k8-15|n8-15]
            int krow = l7 + lg8 * 8;
            int nc = wn * 32 + pi * 16 + lg16 * 8;
            LDSM4T(bfr[pi][0], bfr[pi][1], bfr[pi][2], bfr[pi][3],
                   sb + (uint32_t)(krow * AP_BROW + nc) * 2u);
        }
        #pragma unroll
        for (int mi = 0; mi < 3; ++mi)
            #pragma unroll
            for (int ni = 0; ni < 4; ++ni)
                MMA_F16(acc[mi][ni][0], acc[mi][ni][1], acc[mi][ni][2], acc[mi][ni][3],
                        a[mi][0], a[mi][1], a[mi][2], a[mi][3],
                        bfr[ni >> 1][(ni & 1) * 2], bfr[ni >> 1][(ni & 1) * 2 + 1]);
    }

    int er = lane >> 2;
    int ec = (lane & 3) * 2;
    #pragma unroll
    for (int ni = 0; ni < 4; ++ni) {
        int col = wn * 32 + ni * 8 + ec;
        int p = p0 + (col >> 6), hd = col & 63;
        #pragma unroll
        for (int mi = 0; mi < 3; ++mi) {
            int n = wm * 48 + mi * 16 + er;
            __half* op = out + (((size_t)(b * N_ + n) * P_) + p) * C_ + h * HD_ + hd;
            *(__half2*)op = __floats2half2_rn(acc[mi][ni][0], acc[mi][ni][1]);
            __half* op2 = out + (((size_t)(b * N_ + n + 8) * P_) + p) * C_ + h * HD_ + hd;
            *(__half2*)op2 = __floats2half2_rn(acc[mi][ni][2], acc[mi][ni][3]);
        }
    }
}

// ---------------------------------------------------------------------------
// Weight transpose + fp16 rounding: Wt[n][k] = h(W[k][n]); output ld = 1024
// ---------------------------------------------------------------------------
__global__ void wtrans_kernel(const float* __restrict__ W, __half* __restrict__ Wt, int ldw) {
    __shared__ float t[32][33];
    int n0 = blockIdx.x * 32, k0 = blockIdx.y * 32;
    int tx = threadIdx.x, ty = threadIdx.y;
    #pragma unroll
    for (int i = 0; i < 32; i += 8)
        t[ty + i][tx] = W[(size_t)(k0 + ty + i) * ldw + n0 + tx];
    __syncthreads();
    #pragma unroll
    for (int i = 0; i < 32; i += 8)
        Wt[(size_t)(n0 + ty + i) * C_ + k0 + tx] = __float2half_rn(t[tx][ty + i]);
}

// x -> fp16
__global__ void cvt_kernel(const float* __restrict__ in, __half* __restrict__ out) {
    size_t i = ((size_t)blockIdx.x * 256 + threadIdx.x) * 4;
    float4 v = *(const float4*)(in + i);
    *(__half2*)(out + i)     = __floats2half2_rn(v.x, v.y);
    *(__half2*)(out + i + 2) = __floats2half2_rn(v.z, v.w);
}

__global__ void pool_kernel(const float* __restrict__ x, __half* __restrict__ xbar) {
    int bn = blockIdx.x;
    const float* xp = x + (size_t)bn * P_ * C_;
    for (int c = threadIdx.x; c < C_; c += 256) {
        float s = 0.f;
        #pragma unroll 8
        for (int p = 0; p < P_; ++p) s += xp[(size_t)p * C_ + c];
        xbar[(size_t)bn * C_ + c] = __float2half_rn(s * (1.0f / 64.0f));
    }
}

__global__ void attn_kernel(const float* __restrict__ qk, __half* __restrict__ attn) {
    __shared__ float qs[N_][HD_];
    __shared__ float ks[N_][HD_];
    int b = blockIdx.x >> 4, h = blockIdx.x & 15;
    for (int i = threadIdx.x; i < N_ * HD_; i += 128) {
        int n = i >> 6, d = i & 63;
        const float* base = qk + ((size_t)(b * N_ + n)) * (2 * C_) + h * HD_ + d;
        qs[n][d] = base[0];
        ks[n][d] = base[C_];
    }
    __syncthreads();
    int n = threadIdx.x;
    if (n < N_) {
        __half* row = attn + ((size_t)blockIdx.x * N_ + n) * N_;
        float tmp[N_];
        float mx = -1e30f;
        for (int m = 0; m < N_; ++m) {
            float dot = 0.f;
            #pragma unroll
            for (int d = 0; d < HD_; ++d) dot += qs[n][d] * ks[m][d];
            dot *= 0.125f;
            tmp[m] = dot;
            mx = fmaxf(mx, dot);
        }
        float sum = 0.f;
        for (int m = 0; m < N_; ++m) { float e = __expf(tmp[m] - mx); tmp[m] = e; sum += e; }
        float inv = 1.f / sum;
        for (int m = 0; m < N_; ++m) row[m] = __float2half_rn(tmp[m] * inv);
    }
}

// ---------------------------------------------------------------------------
extern "C" void kernel_launch(void* const* d_in, const int* in_sizes, int n_in,
                              void* d_out, int out_size)
{
    const float* x     = (const float*)d_in[0];
    const float* Wqkv  = (const float*)d_in[1];
    const float* Wproj = (const float*)d_in[2];
    const float* bproj = (const float*)d_in[3];
    float* out = (float*)d_out;

    __half *xh, *xbar, *attnbuf, *vbuf, *obuf, *wqkt, *wvt, *wpt;
    float *qkbuf;
    cudaGetSymbolAddress((void**)&xh,      g_xh);
    cudaGetSymbolAddress((void**)&xbar,    g_xbar);
    cudaGetSymbolAddress((void**)&qkbuf,   g_qk);
    cudaGetSymbolAddress((void**)&attnbuf, g_attnh);
    cudaGetSymbolAddress((void**)&vbuf,    g_vh);
    cudaGetSymbolAddress((void**)&obuf,    g_oh);
    cudaGetSymbolAddress((void**)&wqkt,    g_wqkt);
    cudaGetSymbolAddress((void**)&wvt,     g_wvt);
    cudaGetSymbolAddress((void**)&wpt,     g_wpt);

    cudaFuncSetAttribute(tc_gemm, cudaFuncAttributeMaxDynamicSharedMemorySize, TC_SMEM);
    cudaFuncSetAttribute(apply_tc, cudaFuncAttributeMaxDynamicSharedMemorySize, AP_SMEM);

    // Side streams + fork/join events (created once; host-side only)
    static cudaStream_t s2 = nullptr, s3 = nullptr;
    static cudaEvent_t evRoot = nullptr, evAttn = nullptr, evWpt = nullptr;
    if (!s2) {
        cudaStreamCreateWithFlags(&s2, cudaStreamNonBlocking);
        cudaStreamCreateWithFlags(&s3, cudaStreamNonBlocking);
        cudaEventCreateWithFlags(&evRoot, cudaEventDisableTiming);
        cudaEventCreateWithFlags(&evAttn, cudaEventDisableTiming);
        cudaEventCreateWithFlags(&evWpt, cudaEventDisableTiming);
    }

    cudaEventRecord(evRoot, 0);
    cudaStreamWaitEvent(s2, evRoot, 0);
    cudaStreamWaitEvent(s3, evRoot, 0);

    // s2: qk/attn chain
    wtrans_kernel<<<dim3(64, 32), dim3(32, 8), 0, s2>>>(Wqkv, wqkt, 3 * C_);
    pool_kernel<<<B_ * N_, 256, 0, s2>>>(x, xbar);
    tc_gemm<<<dim3(32, 3), 128, TC_SMEM, s2>>>(xbar, wqkt, qkbuf, nullptr, 1024, C_, C_, 2 * C_, 0);
    attn_kernel<<<B_ * H_, 128, 0, s2>>>(qkbuf, attnbuf);
    cudaEventRecord(evAttn, s2);

    // s3: proj-weight transpose
    wtrans_kernel<<<dim3(32, 32), dim3(32, 8), 0, s3>>>(Wproj, wpt, C_);
    cudaEventRecord(evWpt, s3);

    // main stream: critical path
    wtrans_kernel<<<dim3(32, 32), dim3(32, 8)>>>(Wqkv + 2 * C_, wvt, 3 * C_);
    cvt_kernel<<<M_ROWS, 256>>>(x, xh);
    tc_gemm<<<dim3(16, 192), 128, TC_SMEM>>>(xh, wvt, vbuf, nullptr, 1024, C_, C_, C_, 1);

    cudaStreamWaitEvent(0, evAttn, 0);
    apply_tc<<<dim3(32, 64), 256, AP_SMEM>>>(vbuf, attnbuf, obuf);

    cudaStreamWaitEvent(0, evWpt, 0);
    tc_gemm<<<dim3(16, 192), 128, TC_SMEM>>>(obuf, wpt, out, bproj, 1024, C_, C_, C_, 0);
}

// round 13
// speedup vs baseline: 6.3767x; 1.0442x over previous
#include <cuda_runtime.h>
#include <cuda_fp16.h>
#include <math.h>
#include <stdint.h>

// Problem constants
#define B_ 4
#define N_ 96
#define P_ 64
#define C_ 1024
#define H_ 16
#define HD_ 64
#define M_ROWS (B_*N_*P_)   // 24576
#define MB (N_*P_)          // 6144 rows per batch

// Scratch (device globals: allocation-free contract)
__device__ __half  g_xh[M_ROWS*C_];       // x, fp16
__device__ __half  g_xbar[B_*N_*C_];      // pooled input, fp16
__device__ float   g_qk[B_*N_*2*C_];      // q|k projections (fp32)
__device__ __half  g_attnh[B_*H_*N_*N_];  // softmax probs, fp16
__device__ __half  g_vh[M_ROWS*C_];       // x @ W_v, fp16
__device__ __half  g_oh[M_ROWS*C_];       // attn-applied, fp16
__device__ __half  g_wqkt[2*C_*C_];       // W_qk^T [n][k], fp16
__device__ __half  g_wvt[C_*C_];          // W_v^T
__device__ __half  g_wpt[C_*C_];          // W_proj^T

#define LDSM4(R0,R1,R2,R3,ADDR) \
    asm volatile("ldmatrix.sync.aligned.m8n8.x4.shared.b16 {%0,%1,%2,%3}, [%4];" \
        : "=r"(R0),"=r"(R1),"=r"(R2),"=r"(R3) : "r"(ADDR))
#define LDSM4T(R0,R1,R2,R3,ADDR) \
    asm volatile("ldmatrix.sync.aligned.m8n8.x4.trans.shared.b16 {%0,%1,%2,%3}, [%4];" \
        : "=r"(R0),"=r"(R1),"=r"(R2),"=r"(R3) : "r"(ADDR))

#define MMA_F16(C0,C1,C2,C3,A0,A1,A2,A3,B0,B1) \
    asm volatile("mma.sync.aligned.m16n8k16.row.col.f32.f16.f16.f32 " \
        "{%0,%1,%2,%3}, {%4,%5,%6,%7}, {%8,%9}, {%0,%1,%2,%3};" \
        : "+f"(C0),"+f"(C1),"+f"(C2),"+f"(C3) \
        : "r"(A0),"r"(A1),"r"(A2),"r"(A3),"r"(B0),"r"(B1))

#define CP16(DST, SRC) \
    asm volatile("cp.async.cg.shared.global [%0], [%1], 16;" :: "r"(DST), "l"(SRC) : "memory")
#define CP_COMMIT() asm volatile("cp.async.commit_group;" ::: "memory")
#define CP_WAIT1()  asm volatile("cp.async.wait_group 1;" ::: "memory")

// ---------------------------------------------------------------------------
// FP16 tensor GEMM: C = A[M,K] @ Bt[N,K]^T (+bias), fp32 accum.
// CTA 128x64, 128 threads (2M x 2N warps), warp tile 64x32, KTILE=32,
// 3-stage cp.async, stride-40-half rows.
// ---------------------------------------------------------------------------
#define SROW16 40
#define TA16 (128 * SROW16 * 2)
#define TB16 (64 * SROW16 * 2)
#define ST16 (TA16 + TB16)
#define NST 3
#define TC_SMEM (NST * ST16)               // 46080 B

__global__ void __launch_bounds__(128, 4) tc_gemm(
    const __half* __restrict__ A, const __half* __restrict__ Bt,
    void* __restrict__ Cm, const float* __restrict__ bias,
    int K, int lda, int ldb, int ldc, int outHalf)
{
    extern __shared__ char smem[];
    uint32_t smem_base = (uint32_t)__cvta_generic_to_shared(smem);
    int tid = threadIdx.x;
    int lane = tid & 31, warp = tid >> 5;
    int wm = warp & 1, wn = warp >> 1;

    const __half* Ab = A + (size_t)blockIdx.y * 128 * lda;
    const __half* Bb = Bt + (size_t)blockIdx.x * 64 * ldb;

    float acc[4][4][4];
    #pragma unroll
    for (int i = 0; i < 4; ++i)
        #pragma unroll
        for (int j = 0; j < 4; ++j)
            #pragma unroll
            for (int r = 0; r < 4; ++r) acc[i][j][r] = 0.f;

    auto load_stage = [&](int s, int kt) {
        uint32_t sa = smem_base + s * ST16;
        uint32_t sb = sa + TA16;
        #pragma unroll
        for (int it = 0; it < 4; ++it) {
            int q = tid + it * 128;
            int r = q >> 2, c = q & 3;
            CP16(sa + (uint32_t)(r * SROW16 + c * 8) * 2u,
                 Ab + (size_t)r * lda + kt * 32 + c * 8);
        }
        #pragma unroll
        for (int it = 0; it < 2; ++it) {
            int q = tid + it * 128;
            int r = q >> 2, c = q & 3;
            CP16(sb + (uint32_t)(r * SROW16 + c * 8) * 2u,
                 Bb + (size_t)r * ldb + kt * 32 + c * 8);
        }
    };

    int nt = K / 32;
    load_stage(0, 0); CP_COMMIT();
    load_stage(1, 1); CP_COMMIT();

    int l7 = lane & 7;
    int lg8 = (lane >> 3) & 1;
    int lg16 = lane >> 4;

    #pragma unroll 1
    for (int kt = 0; kt < nt; ++kt) {
        CP_WAIT1();
        __syncthreads();
        if (kt + 2 < nt) load_stage((kt + 2) % NST, kt + 2);
        CP_COMMIT();

        uint32_t sa = smem_base + (kt % NST) * ST16;
        uint32_t sb = sa + TA16;

        #pragma unroll
        for (int ks = 0; ks < 2; ++ks) {
            int k0 = ks * 16;
            uint32_t a[4][4], b[2][4];
            #pragma unroll
            for (int mi = 0; mi < 4; ++mi) {
                int row = wm * 64 + mi * 16 + l7 + lg8 * 8;
                int kc = k0 + lg16 * 8;
                LDSM4(a[mi][0], a[mi][1], a[mi][2], a[mi][3],
                      sa + (uint32_t)(row * SROW16 + kc) * 2u);
            }
            #pragma unroll
            for (int pi = 0; pi < 2; ++pi) {
                int nrow = wn * 32 + pi * 16 + l7 + lg16 * 8;
                int kc = k0 + lg8 * 8;
                LDSM4(b[pi][0], b[pi][1], b[pi][2], b[pi][3],
                      sb + (uint32_t)(nrow * SROW16 + kc) * 2u);
            }
            #pragma unroll
            for (int mi = 0; mi < 4; ++mi)
                #pragma unroll
                for (int ni = 0; ni < 4; ++ni)
                    MMA_F16(acc[mi][ni][0], acc[mi][ni][1], acc[mi][ni][2], acc[mi][ni][3],
                            a[mi][0], a[mi][1], a[mi][2], a[mi][3],
                            b[ni >> 1][(ni & 1) * 2], b[ni >> 1][(ni & 1) * 2 + 1]);
        }
    }

    int cm = blockIdx.y * 128 + wm * 64;
    int cn = blockIdx.x * 64 + wn * 32;
    int er = lane >> 2;
    int ec = (lane & 3) * 2;
    #pragma unroll
    for (int ni = 0; ni < 4; ++ni) {
        int col = cn + ni * 8 + ec;
        float bb0 = bias ? bias[col] : 0.f;
        float bb1 = bias ? bias[col + 1] : 0.f;
        #pragma unroll
        for (int mi = 0; mi < 4; ++mi) {
            int row = cm + mi * 16 + er;
            float v0 = acc[mi][ni][0] + bb0, v1 = acc[mi][ni][1] + bb1;
            float v2 = acc[mi][ni][2] + bb0, v3 = acc[mi][ni][3] + bb1;
            if (outHalf) {
                __half* Ch = (__half*)Cm;
                *(__half2*)(Ch + (size_t)row * ldc + col) = __floats2half2_rn(v0, v1);
                *(__half2*)(Ch + (size_t)(row + 8) * ldc + col) = __floats2half2_rn(v2, v3);
            } else {
                float* Cf = (float*)Cm;
                *(float2*)(Cf + (size_t)row * ldc + col) = make_float2(v0, v1);
                *(float2*)(Cf + (size_t)(row + 8) * ldc + col) = make_float2(v2, v3);
            }
        }
    }
}

// ---------------------------------------------------------------------------
// apply_tc: per (b,h) GEMM  o[n, (p,hd)] = attn[n,m] @ v[m, (p,hd)], batch arg.
// CTA tile 96x128, warp tile 48x32, K=96, 3-stage cp.async.
// ---------------------------------------------------------------------------
#define AP_AROW 24
#define AP_BROW 136
#define AP_TA (96 * AP_AROW * 2)
#define AP_TB (16 * AP_BROW * 2)
#define AP_ST (AP_TA + AP_TB)
#define AP_SMEM (3 * AP_ST)             // 26880 B

__global__ void __launch_bounds__(256) apply_tc(
    const __half* __restrict__ v, const __half* __restrict__ attn,
    __half* __restrict__ out, int bArg)
{
    extern __shared__ char smem[];
    uint32_t smem_base = (uint32_t)__cvta_generic_to_shared(smem);
    int tid = threadIdx.x;
    int lane = tid & 31, warp = tid >> 5;
    int wm = warp & 1, wn = warp >> 1;

    int h = blockIdx.y;
    int b = bArg;
    int bh = b * H_ + h;
    int p0 = blockIdx.x * 2;

    const __half* ab = attn + (size_t)bh * N_ * N_;
    const __half* vb = v + (size_t)b * N_ * P_ * C_ + h * HD_;

    float acc[3][4][4];
    #pragma unroll
    for (int i = 0; i < 3; ++i)
        #pragma unroll
        for (int j = 0; j < 4; ++j)
            #pragma unroll
            for (int r = 0; r < 4; ++r) acc[i][j][r] = 0.f;

    auto load_stage = [&](int s, int kt) {
        uint32_t sa = smem_base + s * AP_ST;
        uint32_t sb = sa + AP_TA;
        if (tid < 192) {
            int r = tid >> 1, c = tid & 1;
            CP16(sa + (uint32_t)(r * AP_AROW + c * 8) * 2u,
                 ab + (size_t)r * N_ + kt * 16 + c * 8);
        }
        {
            int r = tid >> 4, c = tid & 15;
            int m = kt * 16 + r;
            int p = p0 + (c >> 3), hd = (c & 7) * 8;
            CP16(sb + (uint32_t)(r * AP_BROW + c * 8) * 2u,
                 vb + (size_t)m * P_ * C_ + (size_t)p * C_ + hd);
        }
    };

    load_stage(0, 0); CP_COMMIT();
    load_stage(1, 1); CP_COMMIT();

    int l7 = lane & 7;
    int lg8 = (lane >> 3) & 1;
    int lg16 = lane >> 4;

    #pragma unroll 1
    for (int kt = 0; kt < 6; ++kt) {
        CP_WAIT1();
        __syncthreads();
        if (kt + 2 < 6) load_stage((kt + 2) % 3, kt + 2);
        CP_COMMIT();

        uint32_t sa = smem_base + (kt % 3) * AP_ST;
        uint32_t sb = sa + AP_TA;

        uint32_t a[3][4], bfr[2][4];
        #pragma unroll
        for (int mi = 0; mi < 3; ++mi) {
            int row = wm * 48 + mi * 16 + l7 + lg8 * 8;
            int kc = lg16 * 8;
            LDSM4(a[mi][0], a[mi][1], a[mi][2], a[mi][3],
                  sa + (uint32_t)(row * AP_AROW + kc) * 2u);
        }
        #pragma unroll
        for (int pi = 0; pi < 2; ++pi) {
            int krow = l7 + lg8 * 8;
            int nc = wn * 32 + pi * 16 + lg16 * 8;
            LDSM4T(bfr[pi][0], bfr[pi][1], bfr[pi][2], bfr[pi][3],
                   sb + (uint32_t)(krow * AP_BROW + nc) * 2u);
        }
        #pragma unroll
        for (int mi = 0; mi < 3; ++mi)
            #pragma unroll
            for (int ni = 0; ni < 4; ++ni)
                MMA_F16(acc[mi][ni][0], acc[mi][ni][1], acc[mi][ni][2], acc[mi][ni][3],
                        a[mi][0], a[mi][1], a[mi][2], a[mi][3],
                        bfr[ni >> 1][(ni & 1) * 2], bfr[ni >> 1][(ni & 1) * 2 + 1]);
    }

    int er = lane >> 2;
    int ec = (lane & 3) * 2;
    #pragma unroll
    for (int ni = 0; ni < 4; ++ni) {
        int col = wn * 32 + ni * 8 + ec;
        int p = p0 + (col >> 6), hd = col & 63;
        #pragma unroll
        for (int mi = 0; mi < 3; ++mi) {
            int n = wm * 48 + mi * 16 + er;
            __half* op = out + (((size_t)(b * N_ + n) * P_) + p) * C_ + h * HD_ + hd;
            *(__half2*)op = __floats2half2_rn(acc[mi][ni][0], acc[mi][ni][1]);
            __half* op2 = out + (((size_t)(b * N_ + n + 8) * P_) + p) * C_ + h * HD_ + hd;
            *(__half2*)op2 = __floats2half2_rn(acc[mi][ni][2], acc[mi][ni][3]);
        }
    }
}

// ---------------------------------------------------------------------------
// Weight transpose + fp16: Wt[n][k] = h(W[k][n]); output ld = 1024
// ---------------------------------------------------------------------------
__global__ void wtrans_kernel(const float* __restrict__ W, __half* __restrict__ Wt, int ldw) {
    __shared__ float t[32][33];
    int n0 = blockIdx.x * 32, k0 = blockIdx.y * 32;
    int tx = threadIdx.x, ty = threadIdx.y;
    #pragma unroll
    for (int i = 0; i < 32; i += 8)
        t[ty + i][tx] = W[(size_t)(k0 + ty + i) * ldw + n0 + tx];
    __syncthreads();
    #pragma unroll
    for (int i = 0; i < 32; i += 8)
        Wt[(size_t)(n0 + ty + i) * C_ + k0 + tx] = __float2half_rn(t[tx][ty + i]);
}

// x -> fp16 (per-batch chunk)
__global__ void cvt_kernel(const float* __restrict__ in, __half* __restrict__ out) {
    size_t i = ((size_t)blockIdx.x * 256 + threadIdx.x) * 4;
    float4 v = *(const float4*)(in + i);
    *(__half2*)(out + i)     = __floats2half2_rn(v.x, v.y);
    *(__half2*)(out + i + 2) = __floats2half2_rn(v.z, v.w);
}

__global__ void pool_kernel(const float* __restrict__ x, __half* __restrict__ xbar) {
    int bn = blockIdx.x;
    const float* xp = x + (size_t)bn * P_ * C_;
    for (int c = threadIdx.x; c < C_; c += 256) {
        float s = 0.f;
        #pragma unroll 8
        for (int p = 0; p < P_; ++p) s += xp[(size_t)p * C_ + c];
        xbar[(size_t)bn * C_ + c] = __float2half_rn(s * (1.0f / 64.0f));
    }
}

// ---------------------------------------------------------------------------
// attn v2: block=(b,h), 256 threads. Warp per n-row (12 rows/warp), lanes
// split m (3 per lane), shfl softmax. k stored transposed kt[d][m].
// ---------------------------------------------------------------------------
#define ATTN_SMEM (96*64*4 + 64*96*4)   // 49152
__global__ void __launch_bounds__(256) attn_kernel(
    const float* __restrict__ qk, __half* __restrict__ attn)
{
    extern __shared__ float sm[];
    float* qs = sm;               // [96][64]
    float* kt = sm + 96 * 64;     // [64][96]  kt[d][m]
    int b = blockIdx.x >> 4, h = blockIdx.x & 15;
    for (int i = threadIdx.x; i < N_ * HD_; i += 256) {
        int n = i >> 6, d = i & 63;
        const float* base = qk + ((size_t)(b * N_ + n)) * (2 * C_) + h * HD_ + d;
        qs[n * HD_ + d] = base[0];
        kt[d * N_ + n] = base[C_];
    }
    __syncthreads();

    int warp = threadIdx.x >> 5, lane = threadIdx.x & 31;
    int m0 = lane * 3;
    for (int n = warp; n < N_; n += 8) {
        float d0 = 0.f, d1 = 0.f, d2 = 0.f;
        const float* qr = qs + n * HD_;
        #pragma unroll
        for (int d = 0; d < HD_; ++d) {
            float q = qr[d];
            const float* kr = kt + d * N_ + m0;
            d0 += q * kr[0]; d1 += q * kr[1]; d2 += q * kr[2];
        }
        d0 *= 0.125f; d1 *= 0.125f; d2 *= 0.125f;
        float mx = fmaxf(d0, fmaxf(d1, d2));
        #pragma unroll
        for (int o = 16; o; o >>= 1) mx = fmaxf(mx, __shfl_xor_sync(0xFFFFFFFFu, mx, o));
        float e0 = __expf(d0 - mx), e1 = __expf(d1 - mx), e2 = __expf(d2 - mx);
        float s = e0 + e1 + e2;
        #pragma unroll
        for (int o = 16; o; o >>= 1) s += __shfl_xor_sync(0xFFFFFFFFu, s, o);
        float inv = 1.f / s;
        __half* row = attn + ((size_t)blockIdx.x * N_ + n) * N_ + m0;
        row[0] = __float2half_rn(e0 * inv);
        row[1] = __float2half_rn(e1 * inv);
        row[2] = __float2half_rn(e2 * inv);
    }
}

// ---------------------------------------------------------------------------
extern "C" void kernel_launch(void* const* d_in, const int* in_sizes, int n_in,
                              void* d_out, int out_size)
{
    const float* x     = (const float*)d_in[0];
    const float* Wqkv  = (const float*)d_in[1];
    const float* Wproj = (const float*)d_in[2];
    const float* bproj = (const float*)d_in[3];
    float* out = (float*)d_out;

    __half *xh, *xbar, *attnbuf, *vbuf, *obuf, *wqkt, *wvt, *wpt;
    float *qkbuf;
    cudaGetSymbolAddress((void**)&xh,      g_xh);
    cudaGetSymbolAddress((void**)&xbar,    g_xbar);
    cudaGetSymbolAddress((void**)&qkbuf,   g_qk);
    cudaGetSymbolAddress((void**)&attnbuf, g_attnh);
    cudaGetSymbolAddress((void**)&vbuf,    g_vh);
    cudaGetSymbolAddress((void**)&obuf,    g_oh);
    cudaGetSymbolAddress((void**)&wqkt,    g_wqkt);
    cudaGetSymbolAddress((void**)&wvt,     g_wvt);
    cudaGetSymbolAddress((void**)&wpt,     g_wpt);

    cudaFuncSetAttribute(tc_gemm, cudaFuncAttributeMaxDynamicSharedMemorySize, TC_SMEM);
    cudaFuncSetAttribute(apply_tc, cudaFuncAttributeMaxDynamicSharedMemorySize, AP_SMEM);
    cudaFuncSetAttribute(attn_kernel, cudaFuncAttributeMaxDynamicSharedMemorySize, ATTN_SMEM);

    // Streams + events (created once; host-side only).
    static cudaStream_t s2 = nullptr, s3 = nullptr, s4 = nullptr;
    static cudaEvent_t evRoot, evAttn, evWpt, evWvt, evB1, evB2, evB3;
    if (!s2) {
        cudaStreamCreateWithFlags(&s2, cudaStreamNonBlocking);
        cudaStreamCreateWithFlags(&s3, cudaStreamNonBlocking);
        cudaStreamCreateWithFlags(&s4, cudaStreamNonBlocking);
        cudaEventCreateWithFlags(&evRoot, cudaEventDisableTiming);
        cudaEventCreateWithFlags(&evAttn, cudaEventDisableTiming);
        cudaEventCreateWithFlags(&evWpt, cudaEventDisableTiming);
        cudaEventCreateWithFlags(&evWvt, cudaEventDisableTiming);
        cudaEventCreateWithFlags(&evB1, cudaEventDisableTiming);
        cudaEventCreateWithFlags(&evB2, cudaEventDisableTiming);
        cudaEventCreateWithFlags(&evB3, cudaEventDisableTiming);
    }

    // ---- Capture-safe ordering: EVERY cudaEventRecord precedes, in host
    // ---- program order, every cudaStreamWaitEvent that references it.

    cudaEventRecord(evRoot, 0);
    cudaStreamWaitEvent(s2, evRoot, 0);
    cudaStreamWaitEvent(s3, evRoot, 0);
    cudaStreamWaitEvent(s4, evRoot, 0);

    const size_t off1 = (size_t)1 * MB * C_;
    const size_t off2 = (size_t)2 * MB * C_;
    const size_t off3 = (size_t)3 * MB * C_;

    // Prologue phase (all records happen here) -----------------------------
    // main: v-weight transpose
    wtrans_kernel<<<dim3(32, 32), dim3(32, 8)>>>(Wqkv + 2 * C_, wvt, 3 * C_);
    cudaEventRecord(evWvt, 0);
    // s3: proj-weight transpose
    wtrans_kernel<<<dim3(32, 32), dim3(32, 8), 0, s3>>>(Wproj, wpt, C_);
    cudaEventRecord(evWpt, s3);
    // s2: qk/attn chain
    wtrans_kernel<<<dim3(64, 32), dim3(32, 8), 0, s2>>>(Wqkv, wqkt, 3 * C_);
    pool_kernel<<<B_ * N_, 256, 0, s2>>>(x, xbar);
    tc_gemm<<<dim3(32, 3), 128, TC_SMEM, s2>>>(xbar, wqkt, qkbuf, nullptr, 1024, C_, C_, 2 * C_, 0);
    attn_kernel<<<B_ * H_, 256, ATTN_SMEM, s2>>>(qkbuf, attnbuf);
    cudaEventRecord(evAttn, s2);

    // Pipeline phase (only waits on already-recorded events) ---------------
    // main: batch 0
    cvt_kernel<<<MB, 256>>>(x, xh);
    tc_gemm<<<dim3(16, MB / 128), 128, TC_SMEM>>>(xh, wvt, vbuf, nullptr, 1024, C_, C_, C_, 1);
    cudaStreamWaitEvent(0, evAttn, 0);
    apply_tc<<<dim3(32, 16), 256, AP_SMEM>>>(vbuf, attnbuf, obuf, 0);
    cudaStreamWaitEvent(0, evWpt, 0);
    tc_gemm<<<dim3(16, MB / 128), 128, TC_SMEM>>>(obuf, wpt, out, bproj, 1024, C_, C_, C_, 0);

    // s2: batch 1 (attn already on this stream; only needs wvt + wpt)
    cvt_kernel<<<MB, 256, 0, s2>>>(x + off1, xh + off1);
    cudaStreamWaitEvent(s2, evWvt, 0);
    tc_gemm<<<dim3(16, MB / 128), 128, TC_SMEM, s2>>>(xh + off1, wvt, vbuf + off1, nullptr,
                                                      1024, C_, C_, C_, 1);
    apply_tc<<<dim3(32, 16), 256, AP_SMEM, s2>>>(vbuf, attnbuf, obuf, 1);
    cudaStreamWaitEvent(s2, evWpt, 0);
    tc_gemm<<<dim3(16, MB / 128), 128, TC_SMEM, s2>>>(obuf + off1, wpt, out + off1, bproj,
                                                      1024, C_, C_, C_, 0);
    cudaEventRecord(evB1, s2);

    // s3: batch 2 (wpt already on this stream; needs wvt + attn)
    cvt_kernel<<<MB, 256, 0, s3>>>(x + off2, xh + off2);
    cudaStreamWaitEvent(s3, evWvt, 0);
    tc_gemm<<<dim3(16, MB / 128), 128, TC_SMEM, s3>>>(xh + off2, wvt, vbuf + off2, nullptr,
                                                      1024, C_, C_, C_, 1);
    cudaStreamWaitEvent(s3, evAttn, 0);
    apply_tc<<<dim3(32, 16), 256, AP_SMEM, s3>>>(vbuf, attnbuf, obuf, 2);
    tc_gemm<<<dim3(16, MB / 128), 128, TC_SMEM, s3>>>(obuf + off2, wpt, out + off2, bproj,
                                                      1024, C_, C_, C_, 0);
    cudaEventRecord(evB2, s3);

    // s4: batch 3 (needs wvt + attn + wpt)
    cvt_kernel<<<MB, 256, 0, s4>>>(x + off3, xh + off3);
    cudaStreamWaitEvent(s4, evWvt, 0);
    tc_gemm<<<dim3(16, MB / 128), 128, TC_SMEM, s4>>>(xh + off3, wvt, vbuf + off3, nullptr,
                                                      1024, C_, C_, C_, 1);
    cudaStreamWaitEvent(s4, evAttn, 0);
    apply_tc<<<dim3(32, 16), 256, AP_SMEM, s4>>>(vbuf, attnbuf, obuf, 3);
    cudaStreamWaitEvent(s4, evWpt, 0);
    tc_gemm<<<dim3(16, MB / 128), 128, TC_SMEM, s4>>>(obuf + off3, wpt, out + off3, bproj,
                                                      1024, C_, C_, C_, 0);
    cudaEventRecord(evB3, s4);

    // Join all pipelines back to the main stream
    cudaStreamWaitEvent(0, evB1, 0);
    cudaStreamWaitEvent(0, evB2, 0);
    cudaStreamWaitEvent(0, evB3, 0);
}

// round 14
// speedup vs baseline: 7.3997x; 1.1604x over previous
#include <cuda_runtime.h>
#include <cuda_fp16.h>
#include <math.h>
#include <stdint.h>

// Problem constants
#define B_ 4
#define N_ 96
#define P_ 64
#define C_ 1024
#define H_ 16
#define HD_ 64
#define M_ROWS (B_*N_*P_)   // 24576
#define MB (N_*P_)          // 6144 rows per batch

// Scratch (device globals: allocation-free contract)
__device__ __half  g_xh[M_ROWS*C_];       // x, fp16
__device__ __half  g_xbar[B_*N_*C_];      // pooled input, fp16
__device__ float   g_qk[B_*N_*2*C_];      // q|k projections (fp32)
__device__ __half  g_attnh[B_*H_*N_*N_];  // softmax probs, fp16
__device__ __half  g_vh[M_ROWS*C_];       // x @ W_v, fp16
__device__ __half  g_oh[M_ROWS*C_];       // attn-applied, fp16
__device__ __half  g_wqkt[2*C_*C_];       // W_qk^T [n][k], fp16
__device__ __half  g_wvt[C_*C_];          // W_v^T
__device__ __half  g_wpt[C_*C_];          // W_proj^T

#define LDSM4(R0,R1,R2,R3,ADDR) \
    asm volatile("ldmatrix.sync.aligned.m8n8.x4.shared.b16 {%0,%1,%2,%3}, [%4];" \
        : "=r"(R0),"=r"(R1),"=r"(R2),"=r"(R3) : "r"(ADDR))
#define LDSM4T(R0,R1,R2,R3,ADDR) \
    asm volatile("ldmatrix.sync.aligned.m8n8.x4.trans.shared.b16 {%0,%1,%2,%3}, [%4];" \
        : "=r"(R0),"=r"(R1),"=r"(R2),"=r"(R3) : "r"(ADDR))

#define MMA_F16(C0,C1,C2,C3,A0,A1,A2,A3,B0,B1) \
    asm volatile("mma.sync.aligned.m16n8k16.row.col.f32.f16.f16.f32 " \
        "{%0,%1,%2,%3}, {%4,%5,%6,%7}, {%8,%9}, {%0,%1,%2,%3};" \
        : "+f"(C0),"+f"(C1),"+f"(C2),"+f"(C3) \
        : "r"(A0),"r"(A1),"r"(A2),"r"(A3),"r"(B0),"r"(B1))

#define CP16(DST, SRC) \
    asm volatile("cp.async.cg.shared.global [%0], [%1], 16;" :: "r"(DST), "l"(SRC) : "memory")
#define CP_COMMIT() asm volatile("cp.async.commit_group;" ::: "memory")
#define CP_WAIT1()  asm volatile("cp.async.wait_group 1;" ::: "memory")

// ---------------------------------------------------------------------------
// FP16 tensor GEMM v2: C = A[M,K] @ Bt[N,K]^T (+bias), fp32 accum.
// CTA tile 128x128, 128 threads (4 warps: 2M x 2N), warp tile 64x64, KTILE=32,
// 3-stage cp.async. 61 KB smem + <=256 regs -> 2 CTAs/SM (sync bubbles covered
// by the co-resident CTA). ldmatrix:HMMA wavefront ratio 1.0 (was 1.5).
// ---------------------------------------------------------------------------
#define SROW16 40                          // halves per smem row
#define TA16 (128 * SROW16 * 2)            // 10240 B
#define TB16 (128 * SROW16 * 2)            // 10240 B
#define ST16 (TA16 + TB16)                 // 20480 B
#define NST 3
#define TC_SMEM (NST * ST16)               // 61440 B

__global__ void __launch_bounds__(128, 2) tc_gemm(
    const __half* __restrict__ A, const __half* __restrict__ Bt,
    void* __restrict__ Cm, const float* __restrict__ bias,
    int K, int lda, int ldb, int ldc, int outHalf)
{
    extern __shared__ char smem[];
    uint32_t smem_base = (uint32_t)__cvta_generic_to_shared(smem);
    int tid = threadIdx.x;
    int lane = tid & 31, warp = tid >> 5;
    int wm = warp & 1, wn = warp >> 1;

    const __half* Ab = A + (size_t)blockIdx.y * 128 * lda;
    const __half* Bb = Bt + (size_t)blockIdx.x * 128 * ldb;

    float acc[4][8][4];
    #pragma unroll
    for (int i = 0; i < 4; ++i)
        #pragma unroll
        for (int j = 0; j < 8; ++j)
            #pragma unroll
            for (int r = 0; r < 4; ++r) acc[i][j][r] = 0.f;

    auto load_stage = [&](int s, int kt) {
        uint32_t sa = smem_base + s * ST16;
        uint32_t sb = sa + TA16;
        #pragma unroll
        for (int it = 0; it < 4; ++it) {          // A: 512 x 16B
            int q = tid + it * 128;
            int r = q >> 2, c = q & 3;
            CP16(sa + (uint32_t)(r * SROW16 + c * 8) * 2u,
                 Ab + (size_t)r * lda + kt * 32 + c * 8);
        }
        #pragma unroll
        for (int it = 0; it < 4; ++it) {          // B: 512 x 16B
            int q = tid + it * 128;
            int r = q >> 2, c = q & 3;
            CP16(sb + (uint32_t)(r * SROW16 + c * 8) * 2u,
                 Bb + (size_t)r * ldb + kt * 32 + c * 8);
        }
    };

    int nt = K / 32;
    load_stage(0, 0); CP_COMMIT();
    load_stage(1, 1); CP_COMMIT();

    int l7 = lane & 7;
    int lg8 = (lane >> 3) & 1;
    int lg16 = lane >> 4;

    #pragma unroll 1
    for (int kt = 0; kt < nt; ++kt) {
        CP_WAIT1();
        __syncthreads();
        if (kt + 2 < nt) load_stage((kt + 2) % NST, kt + 2);
        CP_COMMIT();

        uint32_t sa = smem_base + (kt % NST) * ST16;
        uint32_t sb = sa + TA16;

        #pragma unroll
        for (int ks = 0; ks < 2; ++ks) {
            int k0 = ks * 16;
            uint32_t a[4][4], b[4][4];
            #pragma unroll
            for (int mi = 0; mi < 4; ++mi) {
                int row = wm * 64 + mi * 16 + l7 + lg8 * 8;
                int kc = k0 + lg16 * 8;
                LDSM4(a[mi][0], a[mi][1], a[mi][2], a[mi][3],
                      sa + (uint32_t)(row * SROW16 + kc) * 2u);
            }
            #pragma unroll
            for (int pi = 0; pi < 4; ++pi) {
                int nrow = wn * 64 + pi * 16 + l7 + lg16 * 8;
                int kc = k0 + lg8 * 8;
                LDSM4(b[pi][0], b[pi][1], b[pi][2], b[pi][3],
                      sb + (uint32_t)(nrow * SROW16 + kc) * 2u);
            }
            #pragma unroll
            for (int mi = 0; mi < 4; ++mi)
                #pragma unroll
                for (int ni = 0; ni < 8; ++ni)
                    MMA_F16(acc[mi][ni][0], acc[mi][ni][1], acc[mi][ni][2], acc[mi][ni][3],
                            a[mi][0], a[mi][1], a[mi][2], a[mi][3],
                            b[ni >> 1][(ni & 1) * 2], b[ni >> 1][(ni & 1) * 2 + 1]);
        }
    }

    int cm = blockIdx.y * 128 + wm * 64;
    int cn = blockIdx.x * 128 + wn * 64;
    int er = lane >> 2;
    int ec = (lane & 3) * 2;
    #pragma unroll
    for (int ni = 0; ni < 8; ++ni) {
        int col = cn + ni * 8 + ec;
        float bb0 = bias ? bias[col] : 0.f;
        float bb1 = bias ? bias[col + 1] : 0.f;
        #pragma unroll
        for (int mi = 0; mi < 4; ++mi) {
            int row = cm + mi * 16 + er;
            float v0 = acc[mi][ni][0] + bb0, v1 = acc[mi][ni][1] + bb1;
            float v2 = acc[mi][ni][2] + bb0, v3 = acc[mi][ni][3] + bb1;
            if (outHalf) {
                __half* Ch = (__half*)Cm;
                *(__half2*)(Ch + (size_t)row * ldc + col) = __floats2half2_rn(v0, v1);
                *(__half2*)(Ch + (size_t)(row + 8) * ldc + col) = __floats2half2_rn(v2, v3);
            } else {
                float* Cf = (float*)Cm;
                *(float2*)(Cf + (size_t)row * ldc + col) = make_float2(v0, v1);
                *(float2*)(Cf + (size_t)(row + 8) * ldc + col) = make_float2(v2, v3);
            }
        }
    }
}

// ---------------------------------------------------------------------------
// apply_tc: per (b,h) GEMM  o[n, (p,hd)] = attn[n,m] @ v[m, (p,hd)], batch arg.
// CTA tile 96x128, warp tile 48x32, K=96, 3-stage cp.async.
// ---------------------------------------------------------------------------
#define AP_AROW 24
#define AP_BROW 136
#define AP_TA (96 * AP_AROW * 2)
#define AP_TB (16 * AP_BROW * 2)
#define AP_ST (AP_TA + AP_TB)
#define AP_SMEM (3 * AP_ST)             // 26880 B

__global__ void __launch_bounds__(256) apply_tc(
    const __half* __restrict__ v, const __half* __restrict__ attn,
    __half* __restrict__ out, int bArg)
{
    extern __shared__ char smem[];
    uint32_t smem_base = (uint32_t)__cvta_generic_to_shared(smem);
    int tid = threadIdx.x;
    int lane = tid & 31, warp = tid >> 5;
    int wm = warp & 1, wn = warp >> 1;

    int h = blockIdx.y;
    int b = bArg;
    int bh = b * H_ + h;
    int p0 = blockIdx.x * 2;

    const __half* ab = attn + (size_t)bh * N_ * N_;
    const __half* vb = v + (size_t)b * N_ * P_ * C_ + h * HD_;

    float acc[3][4][4];
    #pragma unroll
    for (int i = 0; i < 3; ++i)
        #pragma unroll
        for (int j = 0; j < 4; ++j)
            #pragma unroll
            for (int r = 0; r < 4; ++r) acc[i][j][r] = 0.f;

    auto load_stage = [&](int s, int kt) {
        uint32_t sa = smem_base + s * AP_ST;
        uint32_t sb = sa + AP_TA;
        if (tid < 192) {
            int r = tid >> 1, c = tid & 1;
            CP16(sa + (uint32_t)(r * AP_AROW + c * 8) * 2u,
                 ab + (size_t)r * N_ + kt * 16 + c * 8);
        }
        {
            int r = tid >> 4, c = tid & 15;
            int m = kt * 16 + r;
            int p = p0 + (c >> 3), hd = (c & 7) * 8;
            CP16(sb + (uint32_t)(r * AP_BROW + c * 8) * 2u,
                 vb + (size_t)m * P_ * C_ + (size_t)p * C_ + hd);
        }
    };

    load_stage(0, 0); CP_COMMIT();
    load_stage(1, 1); CP_COMMIT();

    int l7 = lane & 7;
    int lg8 = (lane >> 3) & 1;
    int lg16 = lane >> 4;

    #pragma unroll 1
    for (int kt = 0; kt < 6; ++kt) {
        CP_WAIT1();
        __syncthreads();
        if (kt + 2 < 6) load_stage((kt + 2) % 3, kt + 2);
        CP_COMMIT();

        uint32_t sa = smem_base + (kt % 3) * AP_ST;
        uint32_t sb = sa + AP_TA;

        uint32_t a[3][4], bfr[2][4];
        #pragma unroll
        for (int mi = 0; mi < 3; ++mi) {
            int row = wm * 48 + mi * 16 + l7 + lg8 * 8;
            int kc = lg16 * 8;
            LDSM4(a[mi][0], a[mi][1], a[mi][2], a[mi][3],
                  sa + (uint32_t)(row * AP_AROW + kc) * 2u);
        }
        #pragma unroll
        for (int pi = 0; pi < 2; ++pi) {
            int krow = l7 + lg8 * 8;
            int nc = wn * 32 + pi * 16 + lg16 * 8;
            LDSM4T(bfr[pi][0], bfr[pi][1], bfr[pi][2], bfr[pi][3],
                   sb + (uint32_t)(krow * AP_BROW + nc) * 2u);
        }
        #pragma unroll
        for (int mi = 0; mi < 3; ++mi)
            #pragma unroll
            for (int ni = 0; ni < 4; ++ni)
                MMA_F16(acc[mi][ni][0], acc[mi][ni][1], acc[mi][ni][2], acc[mi][ni][3],
                        a[mi][0], a[mi][1], a[mi][2], a[mi][3],
                        bfr[ni >> 1][(ni & 1) * 2], bfr[ni >> 1][(ni & 1) * 2 + 1]);
    }

    int er = lane >> 2;
    int ec = (lane & 3) * 2;
    #pragma unroll
    for (int ni = 0; ni < 4; ++ni) {
        int col = wn * 32 + ni * 8 + ec;
        int p = p0 + (col >> 6), hd = col & 63;
        #pragma unroll
        for (int mi = 0; mi < 3; ++mi) {
            int n = wm * 48 + mi * 16 + er;
            __half* op = out + (((size_t)(b * N_ + n) * P_) + p) * C_ + h * HD_ + hd;
            *(__half2*)op = __floats2half2_rn(acc[mi][ni][0], acc[mi][ni][1]);
            __half* op2 = out + (((size_t)(b * N_ + n + 8) * P_) + p) * C_ + h * HD_ + hd;
            *(__half2*)op2 = __floats2half2_rn(acc[mi][ni][2], acc[mi][ni][3]);
        }
    }
}

// ---------------------------------------------------------------------------
// Weight transpose + fp16: Wt[n][k] = h(W[k][n]); output ld = 1024
// ---------------------------------------------------------------------------
__global__ void wtrans_kernel(const float* __restrict__ W, __half* __restrict__ Wt, int ldw) {
    __shared__ float t[32][33];
    int n0 = blockIdx.x * 32, k0 = blockIdx.y * 32;
    int tx = threadIdx.x, ty = threadIdx.y;
    #pragma unroll
    for (int i = 0; i < 32; i += 8)
        t[ty + i][tx] = W[(size_t)(k0 + ty + i) * ldw + n0 + tx];
    __syncthreads();
    #pragma unroll
    for (int i = 0; i < 32; i += 8)
        Wt[(size_t)(n0 + ty + i) * C_ + k0 + tx] = __float2half_rn(t[tx][ty + i]);
}

// ---------------------------------------------------------------------------
// prep: fused cvt + pool for ONE batch. Block = one n (96 blocks), 256 threads.
// Reads x[b,n,:,:] once; writes fp16 xh and the pooled fp16 xbar row.
// ---------------------------------------------------------------------------
__global__ void __launch_bounds__(256) prep_kernel(
    const float* __restrict__ x, __half* __restrict__ xh,
    __half* __restrict__ xbar, int bArg)
{
    int bn = bArg * N_ + blockIdx.x;
    const float* xp = x + (size_t)bn * P_ * C_;
    __half* xhp = xh + (size_t)bn * P_ * C_;
    int c = threadIdx.x * 4;
    float s0 = 0.f, s1 = 0.f, s2 = 0.f, s3 = 0.f;
    #pragma unroll 4
    for (int p = 0; p < P_; ++p) {
        float4 v = *(const float4*)(xp + (size_t)p * C_ + c);
        s0 += v.x; s1 += v.y; s2 += v.z; s3 += v.w;
        *(__half2*)(xhp + (size_t)p * C_ + c)     = __floats2half2_rn(v.x, v.y);
        *(__half2*)(xhp + (size_t)p * C_ + c + 2) = __floats2half2_rn(v.z, v.w);
    }
    __half* xb = xbar + (size_t)bn * C_ + c;
    *(__half2*)xb       = __floats2half2_rn(s0 * (1.f / 64.f), s1 * (1.f / 64.f));
    *(__half2*)(xb + 2) = __floats2half2_rn(s2 * (1.f / 64.f), s3 * (1.f / 64.f));
}

// ---------------------------------------------------------------------------
// attn v2: block=(b,h), 256 threads; warp per n-row, shfl softmax.
// ---------------------------------------------------------------------------
#define ATTN_SMEM (96*64*4 + 64*96*4)   // 49152
__global__ void __launch_bounds__(256) attn_kernel(
    const float* __restrict__ qk, __half* __restrict__ attn)
{
    extern __shared__ float sm[];
    float* qs = sm;               // [96][64]
    float* kt = sm + 96 * 64;     // [64][96]
    int b = blockIdx.x >> 4, h = blockIdx.x & 15;
    for (int i = threadIdx.x; i < N_ * HD_; i += 256) {
        int n = i >> 6, d = i & 63;
        const float* base = qk + ((size_t)(b * N_ + n)) * (2 * C_) + h * HD_ + d;
        qs[n * HD_ + d] = base[0];
        kt[d * N_ + n] = base[C_];
    }
    __syncthreads();

    int warp = threadIdx.x >> 5, lane = threadIdx.x & 31;
    int m0 = lane * 3;
    for (int n = warp; n < N_; n += 8) {
        float d0 = 0.f, d1 = 0.f, d2 = 0.f;
        const float* qr = qs + n * HD_;
        #pragma unroll
        for (int d = 0; d < HD_; ++d) {
            float q = qr[d];
            const float* kr = kt + d * N_ + m0;
            d0 += q * kr[0]; d1 += q * kr[1]; d2 += q * kr[2];
        }
        d0 *= 0.125f; d1 *= 0.125f; d2 *= 0.125f;
        float mx = fmaxf(d0, fmaxf(d1, d2));
        #pragma unroll
        for (int o = 16; o; o >>= 1) mx = fmaxf(mx, __shfl_xor_sync(0xFFFFFFFFu, mx, o));
        float e0 = __expf(d0 - mx), e1 = __expf(d1 - mx), e2 = __expf(d2 - mx);
        float s = e0 + e1 + e2;
        #pragma unroll
        for (int o = 16; o; o >>= 1) s += __shfl_xor_sync(0xFFFFFFFFu, s, o);
        float inv = 1.f / s;
        __half* row = attn + ((size_t)blockIdx.x * N_ + n) * N_ + m0;
        row[0] = __float2half_rn(e0 * inv);
        row[1] = __float2half_rn(e1 * inv);
        row[2] = __float2half_rn(e2 * inv);
    }
}

// ---------------------------------------------------------------------------
extern "C" void kernel_launch(void* const* d_in, const int* in_sizes, int n_in,
                              void* d_out, int out_size)
{
    const float* x     = (const float*)d_in[0];
    const float* Wqkv  = (const float*)d_in[1];
    const float* Wproj = (const float*)d_in[2];
    const float* bproj = (const float*)d_in[3];
    float* out = (float*)d_out;

    __half *xh, *xbar, *attnbuf, *vbuf, *obuf, *wqkt, *wvt, *wpt;
    float *qkbuf;
    cudaGetSymbolAddress((void**)&xh,      g_xh);
    cudaGetSymbolAddress((void**)&xbar,    g_xbar);
    cudaGetSymbolAddress((void**)&qkbuf,   g_qk);
    cudaGetSymbolAddress((void**)&attnbuf, g_attnh);
    cudaGetSymbolAddress((void**)&vbuf,    g_vh);
    cudaGetSymbolAddress((void**)&obuf,    g_oh);
    cudaGetSymbolAddress((void**)&wqkt,    g_wqkt);
    cudaGetSymbolAddress((void**)&wvt,     g_wvt);
    cudaGetSymbolAddress((void**)&wpt,     g_wpt);

    cudaFuncSetAttribute(tc_gemm, cudaFuncAttributeMaxDynamicSharedMemorySize, TC_SMEM);
    cudaFuncSetAttribute(apply_tc, cudaFuncAttributeMaxDynamicSharedMemorySize, AP_SMEM);
    cudaFuncSetAttribute(attn_kernel, cudaFuncAttributeMaxDynamicSharedMemorySize, ATTN_SMEM);

    // Streams + events (created once; host-side only).
    static cudaStream_t s2 = nullptr, s3 = nullptr, s4 = nullptr;
    static cudaEvent_t evRoot, evAttn, evWpt, evWvt, evP0, evP2, evP3, evB1, evB2, evB3;
    if (!s2) {
        cudaStreamCreateWithFlags(&s2, cudaStreamNonBlocking);
        cudaStreamCreateWithFlags(&s3, cudaStreamNonBlocking);
        cudaStreamCreateWithFlags(&s4, cudaStreamNonBlocking);
        cudaEventCreateWithFlags(&evRoot, cudaEventDisableTiming);
        cudaEventCreateWithFlags(&evAttn, cudaEventDisableTiming);
        cudaEventCreateWithFlags(&evWpt, cudaEventDisableTiming);
        cudaEventCreateWithFlags(&evWvt, cudaEventDisableTiming);
        cudaEventCreateWithFlags(&evP0, cudaEventDisableTiming);
        cudaEventCreateWithFlags(&evP2, cudaEventDisableTiming);
        cudaEventCreateWithFlags(&evP3, cudaEventDisableTiming);
        cudaEventCreateWithFlags(&evB1, cudaEventDisableTiming);
        cudaEventCreateWithFlags(&evB2, cudaEventDisableTiming);
        cudaEventCreateWithFlags(&evB3, cudaEventDisableTiming);
    }

    // ---- Capture-safe ordering: EVERY cudaEventRecord precedes, in host
    // ---- program order, every cudaStreamWaitEvent that references it.

    cudaEventRecord(evRoot, 0);
    cudaStreamWaitEvent(s2, evRoot, 0);
    cudaStreamWaitEvent(s3, evRoot, 0);
    cudaStreamWaitEvent(s4, evRoot, 0);

    const size_t off1 = (size_t)1 * MB * C_;
    const size_t off2 = (size_t)2 * MB * C_;
    const size_t off3 = (size_t)3 * MB * C_;

    // Prologue phase --------------------------------------------------------
    // main: v-weight transpose + batch-0 prep
    wtrans_kernel<<<dim3(32, 32), dim3(32, 8)>>>(Wqkv + 2 * C_, wvt, 3 * C_);
    cudaEventRecord(evWvt, 0);
    prep_kernel<<<N_, 256>>>(x, xh, xbar, 0);
    cudaEventRecord(evP0, 0);
    // s3: proj-weight transpose + batch-2 prep
    wtrans_kernel<<<dim3(32, 32), dim3(32, 8), 0, s3>>>(Wproj, wpt, C_);
    cudaEventRecord(evWpt, s3);
    prep_kernel<<<N_, 256, 0, s3>>>(x, xh, xbar, 2);
    cudaEventRecord(evP2, s3);
    // s4: batch-3 prep
    prep_kernel<<<N_, 256, 0, s4>>>(x, xh, xbar, 3);
    cudaEventRecord(evP3, s4);
    // s2: qk-weight transpose + batch-1 prep, then qk/attn (needs all xbar)
    wtrans_kernel<<<dim3(64, 32), dim3(32, 8), 0, s2>>>(Wqkv, wqkt, 3 * C_);
    prep_kernel<<<N_, 256, 0, s2>>>(x, xh, xbar, 1);
    cudaStreamWaitEvent(s2, evP0, 0);
    cudaStreamWaitEvent(s2, evP2, 0);
    cudaStreamWaitEvent(s2, evP3, 0);
    tc_gemm<<<dim3(16, 3), 128, TC_SMEM, s2>>>(xbar, wqkt, qkbuf, nullptr, 1024, C_, C_, 2 * C_, 0);
    attn_kernel<<<B_ * H_, 256, ATTN_SMEM, s2>>>(qkbuf, attnbuf);
    cudaEventRecord(evAttn, s2);

    // Pipeline phase --------------------------------------------------------
    // main: batch 0 (xh0 + wvt on this stream)
    tc_gemm<<<dim3(8, 48), 128, TC_SMEM>>>(xh, wvt, vbuf, nullptr, 1024, C_, C_, C_, 1);
    cudaStreamWaitEvent(0, evAttn, 0);
    apply_tc<<<dim3(32, 16), 256, AP_SMEM>>>(vbuf, attnbuf, obuf, 0);
    cudaStreamWaitEvent(0, evWpt, 0);
    tc_gemm<<<dim3(8, 48), 128, TC_SMEM>>>(obuf, wpt, out, bproj, 1024, C_, C_, C_, 0);

    // s2: batch 1 (xh1 + attn on this stream; needs wvt + wpt)
    cudaStreamWaitEvent(s2, evWvt, 0);
    tc_gemm<<<dim3(8, 48), 128, TC_SMEM, s2>>>(xh + off1, wvt, vbuf + off1, nullptr,
                                               1024, C_, C_, C_, 1);
    apply_tc<<<dim3(32, 16), 256, AP_SMEM, s2>>>(vbuf, attnbuf, obuf, 1);
    cudaStreamWaitEvent(s2, evWpt, 0);
    tc_gemm<<<dim3(8, 48), 128, TC_SMEM, s2>>>(obuf + off1, wpt, out + off1, bproj,
                                               1024, C_, C_, C_, 0);
    cudaEventRecord(evB1, s2);

    // s3: batch 2 (xh2 + wpt on this stream; needs wvt + attn)
    cudaStreamWaitEvent(s3, evWvt, 0);
    tc_gemm<<<dim3(8, 48), 128, TC_SMEM, s3>>>(xh + off2, wvt, vbuf + off2, nullptr,
                                               1024, C_, C_, C_, 1);
    cudaStreamWaitEvent(s3, evAttn, 0);
    apply_tc<<<dim3(32, 16), 256, AP_SMEM, s3>>>(vbuf, attnbuf, obuf, 2);
    tc_gemm<<<dim3(8, 48), 128, TC_SMEM, s3>>>(obuf + off2, wpt, out + off2, bproj,
                                               1024, C_, C_, C_, 0);
    cudaEventRecord(evB2, s3);

    // s4: batch 3 (xh3 on this stream; needs wvt + attn + wpt)
    cudaStreamWaitEvent(s4, evWvt, 0);
    tc_gemm<<<dim3(8, 48), 128, TC_SMEM, s4>>>(xh + off3, wvt, vbuf + off3, nullptr,
                                               1024, C_, C_, C_, 1);
    cudaStreamWaitEvent(s4, evAttn, 0);
    apply_tc<<<dim3(32, 16), 256, AP_SMEM, s4>>>(vbuf, attnbuf, obuf, 3);
    cudaStreamWaitEvent(s4, evWpt, 0);
    tc_gemm<<<dim3(8, 48), 128, TC_SMEM, s4>>>(obuf + off3, wpt, out + off3, bproj,
                                               1024, C_, C_, C_, 0);
    cudaEventRecord(evB3, s4);

    // Join all pipelines back to the main stream
    cudaStreamWaitEvent(0, evB1, 0);
    cudaStreamWaitEvent(0, evB2, 0);
    cudaStreamWaitEvent(0, evB3, 0);
}